// round 13
// baseline (speedup 1.0000x reference)
#include <cuda_runtime.h>
#include <cuda_fp16.h>
#include <mma.h>
#include <math.h>
#include <stdint.h>

using namespace nvcuda;

#define B_   16
#define S_   1024
#define D_   768
#define NH_  4
#define HD_  192
#define DFF_ 3072
#define NL_  2
#define C_   3
#define BS_  (B_*S_)     // 16384
#define TD_  (3*D_)      // 2304

// ---- output layout (floats) ----
#define O_LA  ((size_t)0)
#define O_LO  ((size_t)49152)
#define O_X   ((size_t)98304)
#define O_SE1 ((size_t)12681216)
#define O_SE2 ((size_t)25264128)
#define O_IA  ((size_t)37847040)
#define O_IO  ((size_t)37847072)
#define O_E1  ((size_t)37847104)
#define O_E2  ((size_t)37859392)

// ---- scratch (device globals) ----
__device__ float g_qkv[(size_t)BS_*TD_];
__device__ __half g_scores16[(size_t)B_*NH_*S_*S_];   // fp16 scores
__device__ float g_z[B_*NH_*S_];                       // 1/rowsum(exp(s))
__device__ float g_w[B_*NH_*S_];
__device__ float g_ctxmean[B_*D_];
__device__ float g_e1[B_*D_];
__device__ float g_e2[B_*D_];
__device__ int   g_idx[B_];
__device__ float g_h1[(size_t)BS_*D_];
__device__ float g_h2[(size_t)BS_*D_];
__device__ float g_tmp[(size_t)BS_*D_];

// fp16 operand buffers
__device__ __half g_ah[(size_t)BS_*D_];
__device__ __half g_ih[(size_t)BS_*DFF_];
__device__ __half g_bh[(size_t)DFF_*D_];
__device__ __half g_qh[(size_t)B_*NH_*S_*HD_];
__device__ __half g_kh[(size_t)B_*NH_*S_*HD_];

// ============================================================
__device__ __forceinline__ uint32_t smem_u32(const void* p) {
    uint32_t a;
    asm("{ .reg .u64 t; cvta.to.shared.u64 t, %1; cvt.u32.u64 %0, t; }" : "=r"(a) : "l"(p));
    return a;
}
__device__ __forceinline__ void cp16(uint32_t dst, const void* src) {
    asm volatile("cp.async.cg.shared.global [%0], [%1], 16;" :: "r"(dst), "l"(src));
}
#define CP_COMMIT() asm volatile("cp.async.commit_group;" ::: "memory")
#define CP_WAIT0()  asm volatile("cp.async.wait_group 0;" ::: "memory")
#define CP_WAIT1()  asm volatile("cp.async.wait_group 1;" ::: "memory")

// ============================================================
// fp16 tensor-core GEMM via wmma. (R11 mainloop, unchanged.)
// EPI: 0 = bias, fp32 C + pack Q/K fp16 per head
//      1 = bias + exact GELU -> fp16 Ch
//      2 = bias + residual -> fp32 C
//      3 = scale + mask -> fp16 Ch (batched, scores; masked = -65504)
// ============================================================
#define SROW   72
#define MATB   18432
#define STAGEB 36864
#define GSMEM  73728

template<int EPI>
__global__ void __launch_bounds__(256, 2) tc_gemm(
    const __half* __restrict__ A, long aBatch,
    const __half* __restrict__ Bw, long bBatch,
    float* __restrict__ C, int ldc, long cBatch,
    __half* __restrict__ Ch,
    const float* __restrict__ bias, const float* __restrict__ resid,
    int K, const int* __restrict__ mask,
    __half* __restrict__ qh, __half* __restrict__ kh)
{
    extern __shared__ char smem[];
    __half* sbf = (__half*)smem;
    float* sf = (float*)smem;
    const uint32_t sb = smem_u32(smem);
    const int tid = threadIdx.x;
    const int wid = tid >> 5;
    const int wm = wid >> 1;       // 0..3
    const int wn = wid & 1;        // 0..1
    const int m0 = blockIdx.y * 128;
    const int n0 = blockIdx.x * 128;
    const int z  = blockIdx.z;

    A  += (size_t)z * aBatch;
    Bw += (size_t)z * bBatch;
    if (C)  C  += (size_t)z * cBatch;
    if (EPI == 3 && Ch) Ch += (size_t)z * cBatch;

    wmma::fragment<wmma::accumulator, 16, 16, 16, float> acc[2][4];
#pragma unroll
    for (int i = 0; i < 2; i++)
#pragma unroll
        for (int j = 0; j < 4; j++) wmma::fill_fragment(acc[i][j], 0.0f);

    const int nk = K >> 6;

    auto load_stage = [&](int st, int k0) {
        uint32_t base = sb + st * STAGEB;
#pragma unroll
        for (int v = tid; v < 2048; v += 256) {
            int mat = v >> 10;
            int rem = v & 1023;
            int r = rem >> 3, cg = rem & 7;
            uint32_t so = mat * MATB + r * 144 + cg * 16;
            const __half* src = mat ? (Bw + (size_t)(n0 + r) * K + k0 + cg * 8)
                                    : (A  + (size_t)(m0 + r) * K + k0 + cg * 8);
            cp16(base + so, src);
        }
    };

    load_stage(0, 0);
    CP_COMMIT();

    for (int c = 0; c < nk; c++) {
        const int st = c & 1;
        if (c + 1 < nk) {
            load_stage(st ^ 1, (c + 1) << 6);
            CP_COMMIT();
            CP_WAIT1();
        } else {
            CP_WAIT0();
        }
        __syncthreads();

        const __half* As = sbf + st * (STAGEB/2);
        const __half* Bs = As + MATB/2;

#pragma unroll
        for (int kst = 0; kst < 4; kst++) {
            wmma::fragment<wmma::matrix_a, 16, 16, 16, __half, wmma::row_major> fa[2];
#pragma unroll
            for (int i = 0; i < 2; i++)
                wmma::load_matrix_sync(fa[i], As + (wm*32 + i*16) * SROW + kst * 16, SROW);
#pragma unroll
            for (int j = 0; j < 4; j++) {
                wmma::fragment<wmma::matrix_b, 16, 16, 16, __half, wmma::col_major> fb;
                wmma::load_matrix_sync(fb, Bs + (wn*64 + j*16) * SROW + kst * 16, SROW);
#pragma unroll
                for (int i = 0; i < 2; i++)
                    wmma::mma_sync(acc[i][j], fa[i], fb, acc[i][j]);
            }
        }
        __syncthreads();
    }

    // stage accumulators to smem
#pragma unroll
    for (int i = 0; i < 2; i++)
#pragma unroll
        for (int j = 0; j < 4; j++)
            wmma::store_matrix_sync(sf + (wm*32 + i*16) * 128 + wn*64 + j*16,
                                    acc[i][j], 128, wmma::mem_row_major);
    __syncthreads();

    // ---- epilogue: 64 elements per thread, coalesced over columns ----
#pragma unroll 4
    for (int it = 0; it < 64; it++) {
        const int idx = it * 256 + tid;
        const int r = idx >> 7;
        const int cc = idx & 127;
        const int row = m0 + r;
        const int col = n0 + cc;
        float v = sf[idx];
        if (EPI == 0) {
            v += bias[col];
            C[(size_t)row * ldc + col] = v;
            if (col < 2 * D_) {
                int b_ = row >> 10, s_ = row & 1023;
                int c2 = (col < D_) ? col : (col - D_);
                int zz = b_ * NH_ + c2 / HD_;
                size_t po = (size_t)zz * (S_*HD_) + (size_t)s_ * HD_ + (c2 % HD_);
                if (col < D_) qh[po] = __float2half(v);
                else          kh[po] = __float2half(v);
            }
        } else if (EPI == 1) {
            v += bias[col];
            v = 0.5f * v * (1.0f + erff(v * 0.70710678118654752f));
            Ch[(size_t)row * ldc + col] = __float2half(v);
        } else if (EPI == 2) {
            v += bias[col] + resid[(size_t)row * ldc + col];
            C[(size_t)row * ldc + col] = v;
        } else {
            v *= 0.07216878364870322f;  // 1/sqrt(192)
            const int b_ = z >> 2;
            if (mask[b_ * S_ + col] == 0) v = -65504.0f;
            Ch[(size_t)row * ldc + col] = __float2half(v);
        }
    }
}

// ============================================================
// fp32 -> fp16
__global__ void cvt_kernel(const float* __restrict__ in,
                           __half* __restrict__ o, size_t n)
{
    size_t i = ((size_t)blockIdx.x * blockDim.x + threadIdx.x) * 4;
    if (i >= n) return;
    float4 v = *(const float4*)(in + i);
    *(__half2*)(o + i)     = __floats2half2_rn(v.x, v.y);
    *(__half2*)(o + i + 2) = __floats2half2_rn(v.z, v.w);
}

// 1/rowsum(exp(s)) per score row (no max subtraction; exp(s) small enough for fp32)
// Row has S_=1024 halves: each of 256 threads reads 2 half2 (4 values).
__global__ void zsum_kernel()
{
    const int row = blockIdx.x;
    const int tid = threadIdx.x;
    const __half* r = g_scores16 + (size_t)row * S_;
    float se = 0.f;
#pragma unroll
    for (int i = 0; i < 2; i++) {
        __half2 h = *(const __half2*)(r + tid*2 + i*512);
        float2 f = __half22float2(h);
        se += __expf(f.x) + __expf(f.y);
    }
    __shared__ float red[256];
    red[tid] = se; __syncthreads();
    for (int st = 128; st > 0; st >>= 1) { if (tid < st) red[tid] += red[tid+st]; __syncthreads(); }
    if (tid == 0) g_z[row] = 1.0f / red[0];
}

// w[z,k] = sum_q exp(s[q,k]) * (1/Z_q)
__global__ void colsum_kernel()
{
    const int zz = blockIdx.x;
    const int col = blockIdx.y * 256 + threadIdx.x;
    __shared__ float sz[S_];
    for (int q = threadIdx.x; q < S_; q += 256) sz[q] = g_z[zz*S_+q];
    __syncthreads();
    float acc = 0.f;
    const __half* sc = g_scores16 + (size_t)zz * S_ * S_ + col;
    for (int q = 0; q < S_; q++)
        acc += __expf(__half2float(sc[(size_t)q * S_])) * sz[q];
    g_w[zz*S_ + col] = acc;
}

__global__ void ctxmean_kernel()
{
    const int z = blockIdx.x;
    const int b = z >> 2, h = z & 3;
    const int d = threadIdx.x;
    __shared__ float w[S_];
    for (int k = d; k < S_; k += 192) w[k] = g_w[z*S_+k];
    __syncthreads();
    float acc = 0.f;
    const float* vb = g_qkv + (size_t)b * S_ * TD_ + 2*D_ + h*HD_ + d;
    for (int k = 0; k < S_; k++) acc += w[k] * vb[(size_t)k * TD_];
    g_ctxmean[b*D_ + h*HD_ + d] = acc * (1.0f / S_);
}

__global__ void idx_kernel(const int* __restrict__ mask)
{
    const int b = blockIdx.x, tid = threadIdx.x;
    __shared__ int red[256];
    int s = 0;
    for (int k = tid; k < S_; k += 256) s += mask[b*S_ + k];
    red[tid] = s; __syncthreads();
    for (int st = 128; st > 0; st >>= 1) { if (tid < st) red[tid] += red[tid+st]; __syncthreads(); }
    if (tid == 0) g_idx[b] = red[0] - 1;
}

__global__ void embed_kernel(
    const float* __restrict__ Wout, const float* __restrict__ bout,
    const float* __restrict__ Wasp, const float* __restrict__ basp,
    const float* __restrict__ Wopi, const float* __restrict__ bopi,
    const float* __restrict__ Wia,  const float* __restrict__ bia,
    const float* __restrict__ Wio,  const float* __restrict__ bio,
    float* __restrict__ out)
{
    const int b = blockIdx.x, tid = threadIdx.x;
    __shared__ float cm[D_], emb[D_], e1s[D_], e2s[D_];
    for (int d = tid; d < D_; d += 256) cm[d] = g_ctxmean[b*D_ + d];
    __syncthreads();
    for (int n = tid; n < D_; n += 256) {
        float a = bout[n];
        const float* wr = Wout + (size_t)n * D_;
        for (int d = 0; d < D_; d++) a += cm[d] * wr[d];
        emb[n] = a;
    }
    __syncthreads();
    for (int n = tid; n < D_; n += 256) {
        float a = basp[n], o = bopi[n];
        const float* wa = Wasp + (size_t)n * D_;
        const float* wo = Wopi + (size_t)n * D_;
        for (int d = 0; d < D_; d++) { a += emb[d] * wa[d]; o += emb[d] * wo[d]; }
        e1s[n] = a; e2s[n] = o;
    }
    __syncthreads();
    for (int d = tid; d < D_; d += 256) {
        g_e1[b*D_ + d] = e1s[d];
        g_e2[b*D_ + d] = e2s[d];
        out[O_E1 + (size_t)b*D_ + d] = e1s[d];
        out[O_E2 + (size_t)b*D_ + d] = e2s[d];
    }
    if (tid < 2) {
        float a = bia[tid];
        const float* w = Wia + (size_t)tid * D_;
        for (int d = 0; d < D_; d++) a += e1s[d] * w[d];
        out[O_IA + b*2 + tid] = a;
    } else if (tid < 4) {
        int c = tid - 2;
        float a = bio[c];
        const float* w = Wio + (size_t)c * D_;
        for (int d = 0; d < D_; d++) a += e2s[d] * w[d];
        out[O_IO + b*2 + c] = a;
    }
}

__global__ void build_se_kernel(const float* __restrict__ x)
{
    const int blk = blockIdx.x;
    const int b = blk >> 10, s = blk & 1023;
    const int idx = g_idx[b];
#pragma unroll
    for (int i = 0; i < 3; i++) {
        int d = threadIdx.x + i * 256;
        float xv = x[(size_t)blk * D_ + d];
        float e1v = g_e1[b*D_ + d], e2v = g_e2[b*D_ + d];
        float v1 = (s == idx) ? e2v : ((s == 0) ? e1v : xv);
        float v2 = (s == 0) ? e1v : ((s == idx) ? e2v : xv);
        g_h1[(size_t)blk * D_ + d] = v1;
        g_h2[(size_t)blk * D_ + d] = v2;
    }
}

// layernorm: fp32 out (+ optional fp16 out for next GEMM A)
__global__ void ln_kernel(const float* __restrict__ in,
                          const float* __restrict__ g, const float* __restrict__ bt,
                          float* __restrict__ outp, __half* __restrict__ oh)
{
    const int row = blockIdx.x, tid = threadIdx.x;
    const float* r = in + (size_t)row * D_;
    float v0 = r[tid], v1 = r[tid+256], v2 = r[tid+512];
    __shared__ float red[256];
    red[tid] = v0 + v1 + v2; __syncthreads();
    for (int st = 128; st > 0; st >>= 1) { if (tid < st) red[tid] += red[tid+st]; __syncthreads(); }
    float mean = red[0] * (1.0f / D_);
    __syncthreads();
    float d0 = v0 - mean, d1 = v1 - mean, d2 = v2 - mean;
    red[tid] = d0*d0 + d1*d1 + d2*d2; __syncthreads();
    for (int st = 128; st > 0; st >>= 1) { if (tid < st) red[tid] += red[tid+st]; __syncthreads(); }
    float rstd = rsqrtf(red[0] * (1.0f / D_) + 1e-12f);
    float o0 = d0 * rstd * g[tid]     + bt[tid];
    float o1 = d1 * rstd * g[tid+256] + bt[tid+256];
    float o2 = d2 * rstd * g[tid+512] + bt[tid+512];
    float* o = outp + (size_t)row * D_;
    o[tid] = o0; o[tid+256] = o1; o[tid+512] = o2;
    if (oh) {
        size_t base = (size_t)row * D_;
        oh[base+tid]     = __float2half(o0);
        oh[base+tid+256] = __float2half(o1);
        oh[base+tid+512] = __float2half(o2);
    }
}

__global__ void logits_kernel(const float* __restrict__ in, const float* __restrict__ W,
                              const float* __restrict__ bias, float* __restrict__ outp)
{
    const int row = blockIdx.x, tid = threadIdx.x;
    __shared__ float srow[D_];
    const float* r = in + (size_t)row * D_;
    srow[tid] = r[tid]; srow[tid+256] = r[tid+256]; srow[tid+512] = r[tid+512];
    __syncthreads();
    float a0 = 0.f, a1 = 0.f, a2 = 0.f;
    for (int d = tid; d < D_; d += 256) {
        float x = srow[d];
        a0 += x * W[d]; a1 += x * W[D_ + d]; a2 += x * W[2*D_ + d];
    }
    __shared__ float red[3][256];
    red[0][tid] = a0; red[1][tid] = a1; red[2][tid] = a2;
    __syncthreads();
    for (int st = 128; st > 0; st >>= 1) {
        if (tid < st) {
            red[0][tid] += red[0][tid+st];
            red[1][tid] += red[1][tid+st];
            red[2][tid] += red[2][tid+st];
        }
        __syncthreads();
    }
    if (tid < 3) outp[(size_t)row * C_ + tid] = red[tid][0] + bias[tid];
}

// ============================================================
extern "C" void kernel_launch(void* const* d_in, const int* in_sizes, int n_in,
                              void* d_out, int out_size)
{
    const float* x        = (const float*)d_in[0];
    const int*   mask     = (const int*)  d_in[1];
    const float* mha_in_w = (const float*)d_in[2];
    const float* mha_in_b = (const float*)d_in[3];
    const float* mha_out_w= (const float*)d_in[4];
    const float* mha_out_b= (const float*)d_in[5];
    const float* asp_w    = (const float*)d_in[6];
    const float* asp_b    = (const float*)d_in[7];
    const float* opi_w    = (const float*)d_in[8];
    const float* opi_b    = (const float*)d_in[9];
    const float* ia_w     = (const float*)d_in[10];
    const float* ia_b     = (const float*)d_in[11];
    const float* io_w     = (const float*)d_in[12];
    const float* io_b     = (const float*)d_in[13];
    const float* fwd_iw   = (const float*)d_in[14];
    const float* fwd_ib   = (const float*)d_in[15];
    const float* fwd_ow   = (const float*)d_in[16];
    const float* fwd_ob   = (const float*)d_in[17];
    const float* fwd_g    = (const float*)d_in[18];
    const float* fwd_bt   = (const float*)d_in[19];
    const float* rev_iw   = (const float*)d_in[20];
    const float* rev_ib   = (const float*)d_in[21];
    const float* rev_ow   = (const float*)d_in[22];
    const float* rev_ob   = (const float*)d_in[23];
    const float* rev_g    = (const float*)d_in[24];
    const float* rev_bt   = (const float*)d_in[25];
    const float* cls_a_w  = (const float*)d_in[26];
    const float* cls_a_b  = (const float*)d_in[27];
    const float* cls_o_w  = (const float*)d_in[28];
    const float* cls_o_b  = (const float*)d_in[29];
    float* out = (float*)d_out;

    float *qkvp, *h1, *h2, *tmp;
    __half *ah, *ih, *bh, *qh, *kh, *sc16;
    cudaGetSymbolAddress((void**)&qkvp, g_qkv);
    cudaGetSymbolAddress((void**)&sc16, g_scores16);
    cudaGetSymbolAddress((void**)&h1,   g_h1);
    cudaGetSymbolAddress((void**)&h2,   g_h2);
    cudaGetSymbolAddress((void**)&tmp,  g_tmp);
    cudaGetSymbolAddress((void**)&ah,   g_ah);
    cudaGetSymbolAddress((void**)&ih,   g_ih);
    cudaGetSymbolAddress((void**)&bh,   g_bh);
    cudaGetSymbolAddress((void**)&qh,   g_qh);
    cudaGetSymbolAddress((void**)&kh,   g_kh);

    cudaFuncSetAttribute(tc_gemm<0>, cudaFuncAttributeMaxDynamicSharedMemorySize, GSMEM);
    cudaFuncSetAttribute(tc_gemm<1>, cudaFuncAttributeMaxDynamicSharedMemorySize, GSMEM);
    cudaFuncSetAttribute(tc_gemm<2>, cudaFuncAttributeMaxDynamicSharedMemorySize, GSMEM);
    cudaFuncSetAttribute(tc_gemm<3>, cudaFuncAttributeMaxDynamicSharedMemorySize, GSMEM);

    auto cvt = [&](const float* src, __half* dst, size_t n) {
        cvt_kernel<<<(unsigned)((n/4 + 255) / 256), 256>>>(src, dst, n);
    };

    // 1) QKV projection; epilogue packs Q/K fp16 per head
    cvt(x, ah, (size_t)BS_ * D_);
    cvt(mha_in_w, bh, (size_t)TD_ * D_);
    tc_gemm<0><<<dim3(TD_/128, BS_/128, 1), 256, GSMEM>>>(
        ah, 0, bh, 0, qkvp, TD_, 0, nullptr,
        mha_in_b, nullptr, D_, nullptr, qh, kh);

    // 2) attention scores -> fp16; zsum (1/rowsum exp) ; colsum ; ctx mean
    tc_gemm<3><<<dim3(S_/128, S_/128, B_*NH_), 256, GSMEM>>>(
        qh, (long)S_*HD_, kh, (long)S_*HD_, nullptr, S_, (long)S_*S_, sc16,
        nullptr, nullptr, HD_, mask, nullptr, nullptr);
    zsum_kernel<<<B_*NH_*S_, 256>>>();
    colsum_kernel<<<dim3(B_*NH_, 4), 256>>>();
    ctxmean_kernel<<<B_*NH_, 192>>>();

    // 3) embedding path
    idx_kernel<<<B_, 256>>>(mask);
    embed_kernel<<<B_, 256>>>(mha_out_w, mha_out_b, asp_w, asp_b, opi_w, opi_b,
                              ia_w, ia_b, io_w, io_b, out);

    // 4) x passthrough
    cudaMemcpyAsync(out + O_X, x, sizeof(float) * (size_t)BS_ * D_, cudaMemcpyDeviceToDevice);

    // 5) build se1/se2
    build_se_kernel<<<BS_, 256>>>(x);

    // 6) decoder stacks on tensor cores
    struct Stack { float* h; const float *iw, *ib, *ow, *ob, *g, *bt; size_t oSE; }
    stacks[2] = {
        { h1, fwd_iw, fwd_ib, fwd_ow, fwd_ob, fwd_g, fwd_bt, O_SE1 },
        { h2, rev_iw, rev_ib, rev_ow, rev_ob, rev_g, rev_bt, O_SE2 },
    };
    for (int s = 0; s < 2; s++) {
        Stack& st = stacks[s];
        cvt(st.h, ah, (size_t)BS_ * D_);
        for (int l = 0; l < NL_; l++) {
            cvt(st.iw + (size_t)l*DFF_*D_, bh, (size_t)DFF_*D_);
            tc_gemm<1><<<dim3(DFF_/128, BS_/128, 1), 256, GSMEM>>>(
                ah, 0, bh, 0, nullptr, DFF_, 0, ih,
                st.ib + (size_t)l*DFF_, nullptr, D_, nullptr, nullptr, nullptr);
            cvt(st.ow + (size_t)l*D_*DFF_, bh, (size_t)D_*DFF_);
            tc_gemm<2><<<dim3(D_/128, BS_/128, 1), 256, GSMEM>>>(
                ih, 0, bh, 0, tmp, D_, 0, nullptr,
                st.ob + (size_t)l*D_, st.h, DFF_, nullptr, nullptr, nullptr);
            bool last = (l == NL_-1);
            float* lnout = last ? (out + st.oSE) : st.h;
            ln_kernel<<<BS_, 256>>>(tmp, st.g + (size_t)l*D_, st.bt + (size_t)l*D_,
                                    lnout, last ? nullptr : ah);
        }
    }

    // 7) classifier logits
    logits_kernel<<<BS_, 256>>>(out + O_SE1, cls_a_w, cls_a_b, out + O_LA);
    logits_kernel<<<BS_, 256>>>(out + O_SE2, cls_o_w, cls_o_b, out + O_LO);
}

// round 14
// speedup vs baseline: 1.0106x; 1.0106x over previous
#include <cuda_runtime.h>
#include <cuda_fp16.h>
#include <mma.h>
#include <math.h>
#include <stdint.h>

using namespace nvcuda;

#define B_   16
#define S_   1024
#define D_   768
#define NH_  4
#define HD_  192
#define DFF_ 3072
#define NL_  2
#define C_   3
#define BS_  (B_*S_)     // 16384
#define TD_  (3*D_)      // 2304

// ---- output layout (floats) ----
#define O_LA  ((size_t)0)
#define O_LO  ((size_t)49152)
#define O_X   ((size_t)98304)
#define O_SE1 ((size_t)12681216)
#define O_SE2 ((size_t)25264128)
#define O_IA  ((size_t)37847040)
#define O_IO  ((size_t)37847072)
#define O_E1  ((size_t)37847104)
#define O_E2  ((size_t)37859392)

// ---- scratch (device globals) ----
__device__ float g_qkv[(size_t)BS_*TD_];               // only V third used
__device__ __half g_scores16[(size_t)B_*NH_*S_*S_];    // fp16 scores
__device__ float g_zr[B_*NH_*S_];                      // rowsum(exp(s)) via atomics
__device__ float g_w[B_*NH_*S_];
__device__ float g_ctxmean[B_*D_];
__device__ float g_e1[B_*D_];
__device__ float g_e2[B_*D_];
__device__ int   g_idx[B_];
__device__ float g_h1[(size_t)BS_*D_];
__device__ float g_h2[(size_t)BS_*D_];
__device__ float g_tmp[(size_t)BS_*D_];

// fp16 operand buffers
__device__ __half g_ah[(size_t)BS_*D_];
__device__ __half g_ah2[(size_t)BS_*D_];
__device__ __half g_ih[(size_t)BS_*DFF_];
__device__ __half g_bh[(size_t)DFF_*D_];
__device__ __half g_qh[(size_t)B_*NH_*S_*HD_];
__device__ __half g_kh[(size_t)B_*NH_*S_*HD_];

// ============================================================
__device__ __forceinline__ uint32_t smem_u32(const void* p) {
    uint32_t a;
    asm("{ .reg .u64 t; cvta.to.shared.u64 t, %1; cvt.u32.u64 %0, t; }" : "=r"(a) : "l"(p));
    return a;
}
__device__ __forceinline__ void cp16(uint32_t dst, const void* src) {
    asm volatile("cp.async.cg.shared.global [%0], [%1], 16;" :: "r"(dst), "l"(src));
}
#define CP_COMMIT() asm volatile("cp.async.commit_group;" ::: "memory")
#define CP_WAIT0()  asm volatile("cp.async.wait_group 0;" ::: "memory")
#define CP_WAIT1()  asm volatile("cp.async.wait_group 1;" ::: "memory")

// ============================================================
// fp16 tensor-core GEMM via wmma. (R11 mainloop.)
// EPI: 0 = bias; pack Q/K fp16 per head; write fp32 C only for V cols
//      1 = bias + exact GELU -> fp16 Ch
//      2 = bias + residual -> fp32 C
//      3 = scale + mask -> fp16 Ch + fused exp-rowsum atomics into zr
// ============================================================
#define SROW   72
#define MATB   18432
#define STAGEB 36864
#define GSMEM  73728   // 2 stages; epilogue: 64KB sf + mask cache above

template<int EPI>
__global__ void __launch_bounds__(256, 2) tc_gemm(
    const __half* __restrict__ A, long aBatch,
    const __half* __restrict__ Bw, long bBatch,
    float* __restrict__ C, int ldc, long cBatch,
    __half* __restrict__ Ch,
    const float* __restrict__ bias, const float* __restrict__ resid,
    int K, const int* __restrict__ mask,
    __half* __restrict__ qh, __half* __restrict__ kh,
    float* __restrict__ zr)
{
    extern __shared__ char smem[];
    __half* sbf = (__half*)smem;
    float* sf = (float*)smem;
    const uint32_t sb = smem_u32(smem);
    const int tid = threadIdx.x;
    const int wid = tid >> 5;
    const int wm = wid >> 1;       // 0..3
    const int wn = wid & 1;        // 0..1
    const int m0 = blockIdx.y * 128;
    const int n0 = blockIdx.x * 128;
    const int z  = blockIdx.z;

    A  += (size_t)z * aBatch;
    Bw += (size_t)z * bBatch;
    if (C)  C  += (size_t)z * cBatch;
    if (EPI == 3 && Ch) Ch += (size_t)z * cBatch;

    wmma::fragment<wmma::accumulator, 16, 16, 16, float> acc[2][4];
#pragma unroll
    for (int i = 0; i < 2; i++)
#pragma unroll
        for (int j = 0; j < 4; j++) wmma::fill_fragment(acc[i][j], 0.0f);

    const int nk = K >> 6;

    auto load_stage = [&](int st, int k0) {
        uint32_t base = sb + st * STAGEB;
#pragma unroll
        for (int v = tid; v < 2048; v += 256) {
            int mat = v >> 10;
            int rem = v & 1023;
            int r = rem >> 3, cg = rem & 7;
            uint32_t so = mat * MATB + r * 144 + cg * 16;
            const __half* src = mat ? (Bw + (size_t)(n0 + r) * K + k0 + cg * 8)
                                    : (A  + (size_t)(m0 + r) * K + k0 + cg * 8);
            cp16(base + so, src);
        }
    };

    load_stage(0, 0);
    CP_COMMIT();

    for (int c = 0; c < nk; c++) {
        const int st = c & 1;
        if (c + 1 < nk) {
            load_stage(st ^ 1, (c + 1) << 6);
            CP_COMMIT();
            CP_WAIT1();
        } else {
            CP_WAIT0();
        }
        __syncthreads();

        const __half* As = sbf + st * (STAGEB/2);
        const __half* Bs = As + MATB/2;

#pragma unroll
        for (int kst = 0; kst < 4; kst++) {
            wmma::fragment<wmma::matrix_a, 16, 16, 16, __half, wmma::row_major> fa[2];
#pragma unroll
            for (int i = 0; i < 2; i++)
                wmma::load_matrix_sync(fa[i], As + (wm*32 + i*16) * SROW + kst * 16, SROW);
#pragma unroll
            for (int j = 0; j < 4; j++) {
                wmma::fragment<wmma::matrix_b, 16, 16, 16, __half, wmma::col_major> fb;
                wmma::load_matrix_sync(fb, Bs + (wn*64 + j*16) * SROW + kst * 16, SROW);
#pragma unroll
                for (int i = 0; i < 2; i++)
                    wmma::mma_sync(acc[i][j], fa[i], fb, acc[i][j]);
            }
        }
        __syncthreads();
    }

    // stage accumulators to smem (first 64KB)
#pragma unroll
    for (int i = 0; i < 2; i++)
#pragma unroll
        for (int j = 0; j < 4; j++)
            wmma::store_matrix_sync(sf + (wm*32 + i*16) * 128 + wn*64 + j*16,
                                    acc[i][j], 128, wmma::mem_row_major);

    // mask cache for EPI3 (above sf region)
    int* maskc = (int*)(smem + 65536);
    if (EPI == 3 && tid < 128) {
        const int b_ = z >> 2;
        maskc[tid] = mask[b_ * S_ + n0 + tid];
    }
    __syncthreads();

    // ---- epilogue: 64 elements per thread, coalesced over columns ----
#pragma unroll 4
    for (int it = 0; it < 64; it++) {
        const int idx = it * 256 + tid;
        const int r = idx >> 7;
        const int cc = idx & 127;
        const int row = m0 + r;
        const int col = n0 + cc;
        float v = sf[idx];
        if (EPI == 0) {
            v += bias[col];
            if (col >= 2 * D_) {
                C[(size_t)row * ldc + col] = v;   // only V third consumed later
            } else {
                int b_ = row >> 10, s_ = row & 1023;
                int c2 = (col < D_) ? col : (col - D_);
                int zz = b_ * NH_ + c2 / HD_;
                size_t po = (size_t)zz * (S_*HD_) + (size_t)s_ * HD_ + (c2 % HD_);
                if (col < D_) qh[po] = __float2half(v);
                else          kh[po] = __float2half(v);
            }
        } else if (EPI == 1) {
            v += bias[col];
            v = 0.5f * v * (1.0f + erff(v * 0.70710678118654752f));
            Ch[(size_t)row * ldc + col] = __float2half(v);
        } else if (EPI == 2) {
            v += bias[col] + resid[(size_t)row * ldc + col];
            C[(size_t)row * ldc + col] = v;
        } else {
            v *= 0.07216878364870322f;  // 1/sqrt(192)
            if (maskc[cc] == 0) v = -65504.0f;
            Ch[(size_t)row * ldc + col] = __float2half(v);
        }
    }

    // ---- EPI3: fused exp-rowsum partials -> atomicAdd into zr ----
    if (EPI == 3) {
        const float scale = 0.07216878364870322f;
        const int r = tid >> 1;           // 0..127
        const int ch = (tid & 1) * 64;    // col half
        float ex = 0.f;
#pragma unroll 8
        for (int cc2 = 0; cc2 < 64; cc2++) {
            int cc = ch + cc2;
            if (maskc[cc] != 0)
                ex += __expf(sf[r * 128 + cc] * scale);
        }
        ex += __shfl_xor_sync(0xffffffffu, ex, 1);
        if ((tid & 1) == 0)
            atomicAdd(&zr[(size_t)z * S_ + m0 + r], ex);
    }
}

// ============================================================
// fp32 -> fp16
__global__ void cvt_kernel(const float* __restrict__ in,
                           __half* __restrict__ o, size_t n)
{
    size_t i = ((size_t)blockIdx.x * blockDim.x + threadIdx.x) * 4;
    if (i >= n) return;
    float4 v = *(const float4*)(in + i);
    *(__half2*)(o + i)     = __floats2half2_rn(v.x, v.y);
    *(__half2*)(o + i + 2) = __floats2half2_rn(v.z, v.w);
}

// w[z,k] = sum_q exp(s[q,k]) / zr_q — 2 cols per thread via half2
__global__ void colsum_kernel()
{
    const int zz = blockIdx.x;
    const int col2 = blockIdx.y * 512 + threadIdx.x * 2;
    __shared__ float sz[S_];
    for (int q = threadIdx.x; q < S_; q += 256) sz[q] = 1.0f / g_zr[zz*S_+q];
    __syncthreads();
    float a0 = 0.f, a1 = 0.f;
    const __half* sc = g_scores16 + (size_t)zz * S_ * S_ + col2;
    for (int q = 0; q < S_; q++) {
        __half2 h = *(const __half2*)(sc + (size_t)q * S_);
        float2 f = __half22float2(h);
        float rz = sz[q];
        a0 += __expf(f.x) * rz;
        a1 += __expf(f.y) * rz;
    }
    g_w[zz*S_ + col2]     = a0;
    g_w[zz*S_ + col2 + 1] = a1;
}

__global__ void ctxmean_kernel()
{
    const int z = blockIdx.x;
    const int b = z >> 2, h = z & 3;
    const int d = threadIdx.x;
    __shared__ float w[S_];
    for (int k = d; k < S_; k += 192) w[k] = g_w[z*S_+k];
    __syncthreads();
    float acc = 0.f;
    const float* vb = g_qkv + (size_t)b * S_ * TD_ + 2*D_ + h*HD_ + d;
    for (int k = 0; k < S_; k++) acc += w[k] * vb[(size_t)k * TD_];
    g_ctxmean[b*D_ + h*HD_ + d] = acc * (1.0f / S_);
}

__global__ void idx_kernel(const int* __restrict__ mask)
{
    const int b = blockIdx.x, tid = threadIdx.x;
    __shared__ int red[256];
    int s = 0;
    for (int k = tid; k < S_; k += 256) s += mask[b*S_ + k];
    red[tid] = s; __syncthreads();
    for (int st = 128; st > 0; st >>= 1) { if (tid < st) red[tid] += red[tid+st]; __syncthreads(); }
    if (tid == 0) g_idx[b] = red[0] - 1;
}

__global__ void embed_kernel(
    const float* __restrict__ Wout, const float* __restrict__ bout,
    const float* __restrict__ Wasp, const float* __restrict__ basp,
    const float* __restrict__ Wopi, const float* __restrict__ bopi,
    const float* __restrict__ Wia,  const float* __restrict__ bia,
    const float* __restrict__ Wio,  const float* __restrict__ bio,
    float* __restrict__ out)
{
    const int b = blockIdx.x, tid = threadIdx.x;
    __shared__ float cm[D_], emb[D_], e1s[D_], e2s[D_];
    for (int d = tid; d < D_; d += 256) cm[d] = g_ctxmean[b*D_ + d];
    __syncthreads();
    for (int n = tid; n < D_; n += 256) {
        float a = bout[n];
        const float* wr = Wout + (size_t)n * D_;
        for (int d = 0; d < D_; d++) a += cm[d] * wr[d];
        emb[n] = a;
    }
    __syncthreads();
    for (int n = tid; n < D_; n += 256) {
        float a = basp[n], o = bopi[n];
        const float* wa = Wasp + (size_t)n * D_;
        const float* wo = Wopi + (size_t)n * D_;
        for (int d = 0; d < D_; d++) { a += emb[d] * wa[d]; o += emb[d] * wo[d]; }
        e1s[n] = a; e2s[n] = o;
    }
    __syncthreads();
    for (int d = tid; d < D_; d += 256) {
        g_e1[b*D_ + d] = e1s[d];
        g_e2[b*D_ + d] = e2s[d];
        out[O_E1 + (size_t)b*D_ + d] = e1s[d];
        out[O_E2 + (size_t)b*D_ + d] = e2s[d];
    }
    if (tid < 2) {
        float a = bia[tid];
        const float* w = Wia + (size_t)tid * D_;
        for (int d = 0; d < D_; d++) a += e1s[d] * w[d];
        out[O_IA + b*2 + tid] = a;
    } else if (tid < 4) {
        int c = tid - 2;
        float a = bio[c];
        const float* w = Wio + (size_t)c * D_;
        for (int d = 0; d < D_; d++) a += e2s[d] * w[d];
        out[O_IO + b*2 + c] = a;
    }
}

// build se1/se2: fp32 h buffers + fp16 A operands for first decoder GEMM
__global__ void build_se_kernel(const float* __restrict__ x,
                                __half* __restrict__ oh1, __half* __restrict__ oh2)
{
    const int blk = blockIdx.x;
    const int b = blk >> 10, s = blk & 1023;
    const int idx = g_idx[b];
#pragma unroll
    for (int i = 0; i < 3; i++) {
        int d = threadIdx.x + i * 256;
        float xv = x[(size_t)blk * D_ + d];
        float e1v = g_e1[b*D_ + d], e2v = g_e2[b*D_ + d];
        float v1 = (s == idx) ? e2v : ((s == 0) ? e1v : xv);
        float v2 = (s == 0) ? e1v : ((s == idx) ? e2v : xv);
        size_t o = (size_t)blk * D_ + d;
        g_h1[o] = v1;
        g_h2[o] = v2;
        oh1[o] = __float2half(v1);
        oh2[o] = __float2half(v2);
    }
}

// layernorm: fp32 out (+ optional fp16 out for next GEMM A)
__global__ void ln_kernel(const float* __restrict__ in,
                          const float* __restrict__ g, const float* __restrict__ bt,
                          float* __restrict__ outp, __half* __restrict__ oh)
{
    const int row = blockIdx.x, tid = threadIdx.x;
    const float* r = in + (size_t)row * D_;
    float v0 = r[tid], v1 = r[tid+256], v2 = r[tid+512];
    __shared__ float red[256];
    red[tid] = v0 + v1 + v2; __syncthreads();
    for (int st = 128; st > 0; st >>= 1) { if (tid < st) red[tid] += red[tid+st]; __syncthreads(); }
    float mean = red[0] * (1.0f / D_);
    __syncthreads();
    float d0 = v0 - mean, d1 = v1 - mean, d2 = v2 - mean;
    red[tid] = d0*d0 + d1*d1 + d2*d2; __syncthreads();
    for (int st = 128; st > 0; st >>= 1) { if (tid < st) red[tid] += red[tid+st]; __syncthreads(); }
    float rstd = rsqrtf(red[0] * (1.0f / D_) + 1e-12f);
    float o0 = d0 * rstd * g[tid]     + bt[tid];
    float o1 = d1 * rstd * g[tid+256] + bt[tid+256];
    float o2 = d2 * rstd * g[tid+512] + bt[tid+512];
    float* o = outp + (size_t)row * D_;
    o[tid] = o0; o[tid+256] = o1; o[tid+512] = o2;
    if (oh) {
        size_t base = (size_t)row * D_;
        oh[base+tid]     = __float2half(o0);
        oh[base+tid+256] = __float2half(o1);
        oh[base+tid+512] = __float2half(o2);
    }
}

__global__ void logits_kernel(const float* __restrict__ in, const float* __restrict__ W,
                              const float* __restrict__ bias, float* __restrict__ outp)
{
    const int row = blockIdx.x, tid = threadIdx.x;
    __shared__ float srow[D_];
    const float* r = in + (size_t)row * D_;
    srow[tid] = r[tid]; srow[tid+256] = r[tid+256]; srow[tid+512] = r[tid+512];
    __syncthreads();
    float a0 = 0.f, a1 = 0.f, a2 = 0.f;
    for (int d = tid; d < D_; d += 256) {
        float x = srow[d];
        a0 += x * W[d]; a1 += x * W[D_ + d]; a2 += x * W[2*D_ + d];
    }
    __shared__ float red[3][256];
    red[0][tid] = a0; red[1][tid] = a1; red[2][tid] = a2;
    __syncthreads();
    for (int st = 128; st > 0; st >>= 1) {
        if (tid < st) {
            red[0][tid] += red[0][tid+st];
            red[1][tid] += red[1][tid+st];
            red[2][tid] += red[2][tid+st];
        }
        __syncthreads();
    }
    if (tid < 3) outp[(size_t)row * C_ + tid] = red[tid][0] + bias[tid];
}

// ============================================================
extern "C" void kernel_launch(void* const* d_in, const int* in_sizes, int n_in,
                              void* d_out, int out_size)
{
    const float* x        = (const float*)d_in[0];
    const int*   mask     = (const int*)  d_in[1];
    const float* mha_in_w = (const float*)d_in[2];
    const float* mha_in_b = (const float*)d_in[3];
    const float* mha_out_w= (const float*)d_in[4];
    const float* mha_out_b= (const float*)d_in[5];
    const float* asp_w    = (const float*)d_in[6];
    const float* asp_b    = (const float*)d_in[7];
    const float* opi_w    = (const float*)d_in[8];
    const float* opi_b    = (const float*)d_in[9];
    const float* ia_w     = (const float*)d_in[10];
    const float* ia_b     = (const float*)d_in[11];
    const float* io_w     = (const float*)d_in[12];
    const float* io_b     = (const float*)d_in[13];
    const float* fwd_iw   = (const float*)d_in[14];
    const float* fwd_ib   = (const float*)d_in[15];
    const float* fwd_ow   = (const float*)d_in[16];
    const float* fwd_ob   = (const float*)d_in[17];
    const float* fwd_g    = (const float*)d_in[18];
    const float* fwd_bt   = (const float*)d_in[19];
    const float* rev_iw   = (const float*)d_in[20];
    const float* rev_ib   = (const float*)d_in[21];
    const float* rev_ow   = (const float*)d_in[22];
    const float* rev_ob   = (const float*)d_in[23];
    const float* rev_g    = (const float*)d_in[24];
    const float* rev_bt   = (const float*)d_in[25];
    const float* cls_a_w  = (const float*)d_in[26];
    const float* cls_a_b  = (const float*)d_in[27];
    const float* cls_o_w  = (const float*)d_in[28];
    const float* cls_o_b  = (const float*)d_in[29];
    float* out = (float*)d_out;

    float *qkvp, *h1, *h2, *tmp, *zrp;
    __half *ah, *ah2, *ih, *bh, *qh, *kh, *sc16;
    cudaGetSymbolAddress((void**)&qkvp, g_qkv);
    cudaGetSymbolAddress((void**)&sc16, g_scores16);
    cudaGetSymbolAddress((void**)&zrp,  g_zr);
    cudaGetSymbolAddress((void**)&h1,   g_h1);
    cudaGetSymbolAddress((void**)&h2,   g_h2);
    cudaGetSymbolAddress((void**)&tmp,  g_tmp);
    cudaGetSymbolAddress((void**)&ah,   g_ah);
    cudaGetSymbolAddress((void**)&ah2,  g_ah2);
    cudaGetSymbolAddress((void**)&ih,   g_ih);
    cudaGetSymbolAddress((void**)&bh,   g_bh);
    cudaGetSymbolAddress((void**)&qh,   g_qh);
    cudaGetSymbolAddress((void**)&kh,   g_kh);

    cudaFuncSetAttribute(tc_gemm<0>, cudaFuncAttributeMaxDynamicSharedMemorySize, GSMEM);
    cudaFuncSetAttribute(tc_gemm<1>, cudaFuncAttributeMaxDynamicSharedMemorySize, GSMEM);
    cudaFuncSetAttribute(tc_gemm<2>, cudaFuncAttributeMaxDynamicSharedMemorySize, GSMEM);
    cudaFuncSetAttribute(tc_gemm<3>, cudaFuncAttributeMaxDynamicSharedMemorySize, GSMEM);

    auto cvt = [&](const float* src, __half* dst, size_t n) {
        cvt_kernel<<<(unsigned)((n/4 + 255) / 256), 256>>>(src, dst, n);
    };

    // zero the exp-rowsum accumulator (graph-capturable memset node)
    cudaMemsetAsync(zrp, 0, sizeof(float) * (size_t)B_ * NH_ * S_);

    // 1) QKV projection; epilogue packs Q/K fp16 per head, writes V fp32 only
    cvt(x, ah, (size_t)BS_ * D_);
    cvt(mha_in_w, bh, (size_t)TD_ * D_);
    tc_gemm<0><<<dim3(TD_/128, BS_/128, 1), 256, GSMEM>>>(
        ah, 0, bh, 0, qkvp, TD_, 0, nullptr,
        mha_in_b, nullptr, D_, nullptr, qh, kh, nullptr);

    // 2) attention scores -> fp16 + fused exp-rowsum; colsum; ctx mean
    tc_gemm<3><<<dim3(S_/128, S_/128, B_*NH_), 256, GSMEM>>>(
        qh, (long)S_*HD_, kh, (long)S_*HD_, nullptr, S_, (long)S_*S_, sc16,
        nullptr, nullptr, HD_, mask, nullptr, nullptr, zrp);
    colsum_kernel<<<dim3(B_*NH_, 2), 256>>>();
    ctxmean_kernel<<<B_*NH_, 192>>>();

    // 3) embedding path
    idx_kernel<<<B_, 256>>>(mask);
    embed_kernel<<<B_, 256>>>(mha_out_w, mha_out_b, asp_w, asp_b, opi_w, opi_b,
                              ia_w, ia_b, io_w, io_b, out);

    // 4) x passthrough
    cudaMemcpyAsync(out + O_X, x, sizeof(float) * (size_t)BS_ * D_, cudaMemcpyDeviceToDevice);

    // 5) build se1/se2 (fp32 + fused fp16 A operands)
    build_se_kernel<<<BS_, 256>>>(x, ah, ah2);

    // 6) decoder stacks on tensor cores
    struct Stack { float* h; __half* a16; const float *iw, *ib, *ow, *ob, *g, *bt; size_t oSE; }
    stacks[2] = {
        { h1, ah,  fwd_iw, fwd_ib, fwd_ow, fwd_ob, fwd_g, fwd_bt, O_SE1 },
        { h2, ah2, rev_iw, rev_ib, rev_ow, rev_ob, rev_g, rev_bt, O_SE2 },
    };
    for (int s = 0; s < 2; s++) {
        Stack& st = stacks[s];
        for (int l = 0; l < NL_; l++) {
            cvt(st.iw + (size_t)l*DFF_*D_, bh, (size_t)DFF_*D_);
            tc_gemm<1><<<dim3(DFF_/128, BS_/128, 1), 256, GSMEM>>>(
                st.a16, 0, bh, 0, nullptr, DFF_, 0, ih,
                st.ib + (size_t)l*DFF_, nullptr, D_, nullptr, nullptr, nullptr, nullptr);
            cvt(st.ow + (size_t)l*D_*DFF_, bh, (size_t)D_*DFF_);
            tc_gemm<2><<<dim3(D_/128, BS_/128, 1), 256, GSMEM>>>(
                ih, 0, bh, 0, tmp, D_, 0, nullptr,
                st.ob + (size_t)l*D_, st.h, DFF_, nullptr, nullptr, nullptr, nullptr);
            bool last = (l == NL_-1);
            float* lnout = last ? (out + st.oSE) : st.h;
            ln_kernel<<<BS_, 256>>>(tmp, st.g + (size_t)l*D_, st.bt + (size_t)l*D_,
                                    lnout, last ? nullptr : st.a16);
        }
    }

    // 7) classifier logits
    logits_kernel<<<BS_, 256>>>(out + O_SE1, cls_a_w, cls_a_b, out + O_LA);
    logits_kernel<<<BS_, 256>>>(out + O_SE2, cls_o_w, cls_o_b, out + O_LO);
}

// round 15
// speedup vs baseline: 1.0435x; 1.0326x over previous
#include <cuda_runtime.h>
#include <cuda_fp16.h>
#include <mma.h>
#include <math.h>
#include <stdint.h>

using namespace nvcuda;

#define B_   16
#define S_   1024
#define D_   768
#define NH_  4
#define HD_  192
#define DFF_ 3072
#define NL_  2
#define C_   3
#define BS_  (B_*S_)     // 16384
#define TD_  (3*D_)      // 2304

// ---- output layout (floats) ----
#define O_LA  ((size_t)0)
#define O_LO  ((size_t)49152)
#define O_X   ((size_t)98304)
#define O_SE1 ((size_t)12681216)
#define O_SE2 ((size_t)25264128)
#define O_IA  ((size_t)37847040)
#define O_IO  ((size_t)37847072)
#define O_E1  ((size_t)37847104)
#define O_E2  ((size_t)37859392)

// ---- scratch (device globals) ----
__device__ float g_qkv[(size_t)BS_*TD_];               // only V third used
__device__ __half g_scores16[(size_t)B_*NH_*S_*S_];    // fp16 scores
__device__ float g_zr[B_*NH_*S_];                      // rowsum(exp(s)) via atomics
__device__ float g_w[B_*NH_*S_];
__device__ float g_ctxmean[B_*D_];
__device__ float g_e1[B_*D_];
__device__ float g_e2[B_*D_];
__device__ int   g_idx[B_];
__device__ float g_h1[(size_t)BS_*D_];
__device__ float g_h2[(size_t)BS_*D_];
__device__ float g_tmp[(size_t)BS_*D_];

// fp16 operand buffers
__device__ __half g_ah[(size_t)BS_*D_];
__device__ __half g_ah2[(size_t)BS_*D_];
__device__ __half g_ih[(size_t)BS_*DFF_];
__device__ __half g_bh[(size_t)DFF_*D_];
__device__ __half g_qh[(size_t)B_*NH_*S_*HD_];
__device__ __half g_kh[(size_t)B_*NH_*S_*HD_];

// ============================================================
__device__ __forceinline__ uint32_t smem_u32(const void* p) {
    uint32_t a;
    asm("{ .reg .u64 t; cvta.to.shared.u64 t, %1; cvt.u32.u64 %0, t; }" : "=r"(a) : "l"(p));
    return a;
}
__device__ __forceinline__ void cp16(uint32_t dst, const void* src) {
    asm volatile("cp.async.cg.shared.global [%0], [%1], 16;" :: "r"(dst), "l"(src));
}
#define CP_COMMIT() asm volatile("cp.async.commit_group;" ::: "memory")
#define CP_WAIT0()  asm volatile("cp.async.wait_group 0;" ::: "memory")
#define CP_WAIT1()  asm volatile("cp.async.wait_group 1;" ::: "memory")

// ============================================================
// fp16 tensor-core GEMM via wmma. (R11 mainloop.)
// EPI: 0 = bias; pack Q/K fp16 per head; write fp32 C only for V cols
//      1 = bias + exact GELU -> fp16 Ch
//      2 = bias + residual -> fp32 C
//      3 = scale + mask -> fp16 Ch + fused exp-rowsum atomics into zr
// ============================================================
#define SROW   72
#define MATB   18432
#define STAGEB 36864
#define GSMEM  73728   // 2 stages; epilogue: 64KB sf + mask cache above

template<int EPI>
__global__ void __launch_bounds__(256, 2) tc_gemm(
    const __half* __restrict__ A, long aBatch,
    const __half* __restrict__ Bw, long bBatch,
    float* __restrict__ C, int ldc, long cBatch,
    __half* __restrict__ Ch,
    const float* __restrict__ bias, const float* __restrict__ resid,
    int K, const int* __restrict__ mask,
    __half* __restrict__ qh, __half* __restrict__ kh,
    float* __restrict__ zr)
{
    extern __shared__ char smem[];
    __half* sbf = (__half*)smem;
    float* sf = (float*)smem;
    const uint32_t sb = smem_u32(smem);
    const int tid = threadIdx.x;
    const int wid = tid >> 5;
    const int wm = wid >> 1;       // 0..3
    const int wn = wid & 1;        // 0..1
    const int m0 = blockIdx.y * 128;
    const int n0 = blockIdx.x * 128;
    const int z  = blockIdx.z;

    A  += (size_t)z * aBatch;
    Bw += (size_t)z * bBatch;
    if (C)  C  += (size_t)z * cBatch;
    if (EPI == 3 && Ch) Ch += (size_t)z * cBatch;

    wmma::fragment<wmma::accumulator, 16, 16, 16, float> acc[2][4];
#pragma unroll
    for (int i = 0; i < 2; i++)
#pragma unroll
        for (int j = 0; j < 4; j++) wmma::fill_fragment(acc[i][j], 0.0f);

    const int nk = K >> 6;

    auto load_stage = [&](int st, int k0) {
        uint32_t base = sb + st * STAGEB;
#pragma unroll
        for (int v = tid; v < 2048; v += 256) {
            int mat = v >> 10;
            int rem = v & 1023;
            int r = rem >> 3, cg = rem & 7;
            uint32_t so = mat * MATB + r * 144 + cg * 16;
            const __half* src = mat ? (Bw + (size_t)(n0 + r) * K + k0 + cg * 8)
                                    : (A  + (size_t)(m0 + r) * K + k0 + cg * 8);
            cp16(base + so, src);
        }
    };

    load_stage(0, 0);
    CP_COMMIT();

    for (int c = 0; c < nk; c++) {
        const int st = c & 1;
        if (c + 1 < nk) {
            load_stage(st ^ 1, (c + 1) << 6);
            CP_COMMIT();
            CP_WAIT1();
        } else {
            CP_WAIT0();
        }
        __syncthreads();

        const __half* As = sbf + st * (STAGEB/2);
        const __half* Bs = As + MATB/2;

#pragma unroll
        for (int kst = 0; kst < 4; kst++) {
            wmma::fragment<wmma::matrix_a, 16, 16, 16, __half, wmma::row_major> fa[2];
#pragma unroll
            for (int i = 0; i < 2; i++)
                wmma::load_matrix_sync(fa[i], As + (wm*32 + i*16) * SROW + kst * 16, SROW);
#pragma unroll
            for (int j = 0; j < 4; j++) {
                wmma::fragment<wmma::matrix_b, 16, 16, 16, __half, wmma::col_major> fb;
                wmma::load_matrix_sync(fb, Bs + (wn*64 + j*16) * SROW + kst * 16, SROW);
#pragma unroll
                for (int i = 0; i < 2; i++)
                    wmma::mma_sync(acc[i][j], fa[i], fb, acc[i][j]);
            }
        }
        __syncthreads();
    }

    // stage accumulators to smem (first 64KB)
#pragma unroll
    for (int i = 0; i < 2; i++)
#pragma unroll
        for (int j = 0; j < 4; j++)
            wmma::store_matrix_sync(sf + (wm*32 + i*16) * 128 + wn*64 + j*16,
                                    acc[i][j], 128, wmma::mem_row_major);

    // mask cache for EPI3 (above sf region)
    int* maskc = (int*)(smem + 65536);
    if (EPI == 3 && tid < 128) {
        const int b_ = z >> 2;
        maskc[tid] = mask[b_ * S_ + n0 + tid];
    }
    __syncthreads();

    // ---- epilogue: 64 elements per thread, coalesced over columns ----
#pragma unroll 4
    for (int it = 0; it < 64; it++) {
        const int idx = it * 256 + tid;
        const int r = idx >> 7;
        const int cc = idx & 127;
        const int row = m0 + r;
        const int col = n0 + cc;
        float v = sf[idx];
        if (EPI == 0) {
            v += bias[col];
            if (col >= 2 * D_) {
                C[(size_t)row * ldc + col] = v;   // only V third consumed later
            } else {
                int b_ = row >> 10, s_ = row & 1023;
                int c2 = (col < D_) ? col : (col - D_);
                int zz = b_ * NH_ + c2 / HD_;
                size_t po = (size_t)zz * (S_*HD_) + (size_t)s_ * HD_ + (c2 % HD_);
                if (col < D_) qh[po] = __float2half(v);
                else          kh[po] = __float2half(v);
            }
        } else if (EPI == 1) {
            v += bias[col];
            v = 0.5f * v * (1.0f + erff(v * 0.70710678118654752f));
            Ch[(size_t)row * ldc + col] = __float2half(v);
        } else if (EPI == 2) {
            v += bias[col] + resid[(size_t)row * ldc + col];
            C[(size_t)row * ldc + col] = v;
        } else {
            v *= 0.07216878364870322f;  // 1/sqrt(192)
            if (maskc[cc] == 0) v = -65504.0f;
            Ch[(size_t)row * ldc + col] = __float2half(v);
        }
    }

    // ---- EPI3: fused exp-rowsum partials -> atomicAdd into zr ----
    // thread t owns row r = t&127, column half base = (t>>7)*64,
    // reads with row-rotation (cc2 + r) & 63 -> conflict-free banks.
    if (EPI == 3) {
        const float scale = 0.07216878364870322f;
        const int r = tid & 127;
        const int base = (tid >> 7) * 64;
        float ex = 0.f;
#pragma unroll 8
        for (int cc2 = 0; cc2 < 64; cc2++) {
            int col = base + ((cc2 + r) & 63);
            if (maskc[col] != 0)
                ex += __expf(sf[r * 128 + col] * scale);
        }
        atomicAdd(&zr[(size_t)z * S_ + m0 + r], ex);
    }
}

// ============================================================
// fp32 -> fp16
__global__ void cvt_kernel(const float* __restrict__ in,
                           __half* __restrict__ o, size_t n)
{
    size_t i = ((size_t)blockIdx.x * blockDim.x + threadIdx.x) * 4;
    if (i >= n) return;
    float4 v = *(const float4*)(in + i);
    *(__half2*)(o + i)     = __floats2half2_rn(v.x, v.y);
    *(__half2*)(o + i + 2) = __floats2half2_rn(v.z, v.w);
}

// w[z,k] = sum_q exp(s[q,k]) / zr_q — 2 cols per thread via half2
__global__ void colsum_kernel()
{
    const int zz = blockIdx.x;
    const int col2 = blockIdx.y * 512 + threadIdx.x * 2;
    __shared__ float sz[S_];
    for (int q = threadIdx.x; q < S_; q += 256) sz[q] = 1.0f / g_zr[zz*S_+q];
    __syncthreads();
    float a0 = 0.f, a1 = 0.f;
    const __half* sc = g_scores16 + (size_t)zz * S_ * S_ + col2;
    for (int q = 0; q < S_; q++) {
        __half2 h = *(const __half2*)(sc + (size_t)q * S_);
        float2 f = __half22float2(h);
        float rz = sz[q];
        a0 += __expf(f.x) * rz;
        a1 += __expf(f.y) * rz;
    }
    g_w[zz*S_ + col2]     = a0;
    g_w[zz*S_ + col2 + 1] = a1;
}

__global__ void ctxmean_kernel()
{
    const int z = blockIdx.x;
    const int b = z >> 2, h = z & 3;
    const int d = threadIdx.x;
    __shared__ float w[S_];
    for (int k = d; k < S_; k += 192) w[k] = g_w[z*S_+k];
    __syncthreads();
    float acc = 0.f;
    const float* vb = g_qkv + (size_t)b * S_ * TD_ + 2*D_ + h*HD_ + d;
    for (int k = 0; k < S_; k++) acc += w[k] * vb[(size_t)k * TD_];
    g_ctxmean[b*D_ + h*HD_ + d] = acc * (1.0f / S_);
}

__global__ void idx_kernel(const int* __restrict__ mask)
{
    const int b = blockIdx.x, tid = threadIdx.x;
    __shared__ int red[256];
    int s = 0;
    for (int k = tid; k < S_; k += 256) s += mask[b*S_ + k];
    red[tid] = s; __syncthreads();
    for (int st = 128; st > 0; st >>= 1) { if (tid < st) red[tid] += red[tid+st]; __syncthreads(); }
    if (tid == 0) g_idx[b] = red[0] - 1;
}

__global__ void embed_kernel(
    const float* __restrict__ Wout, const float* __restrict__ bout,
    const float* __restrict__ Wasp, const float* __restrict__ basp,
    const float* __restrict__ Wopi, const float* __restrict__ bopi,
    const float* __restrict__ Wia,  const float* __restrict__ bia,
    const float* __restrict__ Wio,  const float* __restrict__ bio,
    float* __restrict__ out)
{
    const int b = blockIdx.x, tid = threadIdx.x;
    __shared__ float cm[D_], emb[D_], e1s[D_], e2s[D_];
    for (int d = tid; d < D_; d += 256) cm[d] = g_ctxmean[b*D_ + d];
    __syncthreads();
    for (int n = tid; n < D_; n += 256) {
        float a = bout[n];
        const float* wr = Wout + (size_t)n * D_;
        for (int d = 0; d < D_; d++) a += cm[d] * wr[d];
        emb[n] = a;
    }
    __syncthreads();
    for (int n = tid; n < D_; n += 256) {
        float a = basp[n], o = bopi[n];
        const float* wa = Wasp + (size_t)n * D_;
        const float* wo = Wopi + (size_t)n * D_;
        for (int d = 0; d < D_; d++) { a += emb[d] * wa[d]; o += emb[d] * wo[d]; }
        e1s[n] = a; e2s[n] = o;
    }
    __syncthreads();
    for (int d = tid; d < D_; d += 256) {
        g_e1[b*D_ + d] = e1s[d];
        g_e2[b*D_ + d] = e2s[d];
        out[O_E1 + (size_t)b*D_ + d] = e1s[d];
        out[O_E2 + (size_t)b*D_ + d] = e2s[d];
    }
    if (tid < 2) {
        float a = bia[tid];
        const float* w = Wia + (size_t)tid * D_;
        for (int d = 0; d < D_; d++) a += e1s[d] * w[d];
        out[O_IA + b*2 + tid] = a;
    } else if (tid < 4) {
        int c = tid - 2;
        float a = bio[c];
        const float* w = Wio + (size_t)c * D_;
        for (int d = 0; d < D_; d++) a += e2s[d] * w[d];
        out[O_IO + b*2 + c] = a;
    }
}

// build se1/se2: fp32 h buffers + fp16 A operands for first decoder GEMM
__global__ void build_se_kernel(const float* __restrict__ x,
                                __half* __restrict__ oh1, __half* __restrict__ oh2)
{
    const int blk = blockIdx.x;
    const int b = blk >> 10, s = blk & 1023;
    const int idx = g_idx[b];
#pragma unroll
    for (int i = 0; i < 3; i++) {
        int d = threadIdx.x + i * 256;
        float xv = x[(size_t)blk * D_ + d];
        float e1v = g_e1[b*D_ + d], e2v = g_e2[b*D_ + d];
        float v1 = (s == idx) ? e2v : ((s == 0) ? e1v : xv);
        float v2 = (s == 0) ? e1v : ((s == idx) ? e2v : xv);
        size_t o = (size_t)blk * D_ + d;
        g_h1[o] = v1;
        g_h2[o] = v2;
        oh1[o] = __float2half(v1);
        oh2[o] = __float2half(v2);
    }
}

// layernorm: fp32 out (+ optional fp16 out for next GEMM A)
__global__ void ln_kernel(const float* __restrict__ in,
                          const float* __restrict__ g, const float* __restrict__ bt,
                          float* __restrict__ outp, __half* __restrict__ oh)
{
    const int row = blockIdx.x, tid = threadIdx.x;
    const float* r = in + (size_t)row * D_;
    float v0 = r[tid], v1 = r[tid+256], v2 = r[tid+512];
    __shared__ float red[256];
    red[tid] = v0 + v1 + v2; __syncthreads();
    for (int st = 128; st > 0; st >>= 1) { if (tid < st) red[tid] += red[tid+st]; __syncthreads(); }
    float mean = red[0] * (1.0f / D_);
    __syncthreads();
    float d0 = v0 - mean, d1 = v1 - mean, d2 = v2 - mean;
    red[tid] = d0*d0 + d1*d1 + d2*d2; __syncthreads();
    for (int st = 128; st > 0; st >>= 1) { if (tid < st) red[tid] += red[tid+st]; __syncthreads(); }
    float rstd = rsqrtf(red[0] * (1.0f / D_) + 1e-12f);
    float o0 = d0 * rstd * g[tid]     + bt[tid];
    float o1 = d1 * rstd * g[tid+256] + bt[tid+256];
    float o2 = d2 * rstd * g[tid+512] + bt[tid+512];
    float* o = outp + (size_t)row * D_;
    o[tid] = o0; o[tid+256] = o1; o[tid+512] = o2;
    if (oh) {
        size_t base = (size_t)row * D_;
        oh[base+tid]     = __float2half(o0);
        oh[base+tid+256] = __float2half(o1);
        oh[base+tid+512] = __float2half(o2);
    }
}

__global__ void logits_kernel(const float* __restrict__ in, const float* __restrict__ W,
                              const float* __restrict__ bias, float* __restrict__ outp)
{
    const int row = blockIdx.x, tid = threadIdx.x;
    __shared__ float srow[D_];
    const float* r = in + (size_t)row * D_;
    srow[tid] = r[tid]; srow[tid+256] = r[tid+256]; srow[tid+512] = r[tid+512];
    __syncthreads();
    float a0 = 0.f, a1 = 0.f, a2 = 0.f;
    for (int d = tid; d < D_; d += 256) {
        float x = srow[d];
        a0 += x * W[d]; a1 += x * W[D_ + d]; a2 += x * W[2*D_ + d];
    }
    __shared__ float red[3][256];
    red[0][tid] = a0; red[1][tid] = a1; red[2][tid] = a2;
    __syncthreads();
    for (int st = 128; st > 0; st >>= 1) {
        if (tid < st) {
            red[0][tid] += red[0][tid+st];
            red[1][tid] += red[1][tid+st];
            red[2][tid] += red[2][tid+st];
        }
        __syncthreads();
    }
    if (tid < 3) outp[(size_t)row * C_ + tid] = red[tid][0] + bias[tid];
}

// ============================================================
extern "C" void kernel_launch(void* const* d_in, const int* in_sizes, int n_in,
                              void* d_out, int out_size)
{
    const float* x        = (const float*)d_in[0];
    const int*   mask     = (const int*)  d_in[1];
    const float* mha_in_w = (const float*)d_in[2];
    const float* mha_in_b = (const float*)d_in[3];
    const float* mha_out_w= (const float*)d_in[4];
    const float* mha_out_b= (const float*)d_in[5];
    const float* asp_w    = (const float*)d_in[6];
    const float* asp_b    = (const float*)d_in[7];
    const float* opi_w    = (const float*)d_in[8];
    const float* opi_b    = (const float*)d_in[9];
    const float* ia_w     = (const float*)d_in[10];
    const float* ia_b     = (const float*)d_in[11];
    const float* io_w     = (const float*)d_in[12];
    const float* io_b     = (const float*)d_in[13];
    const float* fwd_iw   = (const float*)d_in[14];
    const float* fwd_ib   = (const float*)d_in[15];
    const float* fwd_ow   = (const float*)d_in[16];
    const float* fwd_ob   = (const float*)d_in[17];
    const float* fwd_g    = (const float*)d_in[18];
    const float* fwd_bt   = (const float*)d_in[19];
    const float* rev_iw   = (const float*)d_in[20];
    const float* rev_ib   = (const float*)d_in[21];
    const float* rev_ow   = (const float*)d_in[22];
    const float* rev_ob   = (const float*)d_in[23];
    const float* rev_g    = (const float*)d_in[24];
    const float* rev_bt   = (const float*)d_in[25];
    const float* cls_a_w  = (const float*)d_in[26];
    const float* cls_a_b  = (const float*)d_in[27];
    const float* cls_o_w  = (const float*)d_in[28];
    const float* cls_o_b  = (const float*)d_in[29];
    float* out = (float*)d_out;

    float *qkvp, *h1, *h2, *tmp, *zrp;
    __half *ah, *ah2, *ih, *bh, *qh, *kh, *sc16;
    cudaGetSymbolAddress((void**)&qkvp, g_qkv);
    cudaGetSymbolAddress((void**)&sc16, g_scores16);
    cudaGetSymbolAddress((void**)&zrp,  g_zr);
    cudaGetSymbolAddress((void**)&h1,   g_h1);
    cudaGetSymbolAddress((void**)&h2,   g_h2);
    cudaGetSymbolAddress((void**)&tmp,  g_tmp);
    cudaGetSymbolAddress((void**)&ah,   g_ah);
    cudaGetSymbolAddress((void**)&ah2,  g_ah2);
    cudaGetSymbolAddress((void**)&ih,   g_ih);
    cudaGetSymbolAddress((void**)&bh,   g_bh);
    cudaGetSymbolAddress((void**)&qh,   g_qh);
    cudaGetSymbolAddress((void**)&kh,   g_kh);

    cudaFuncSetAttribute(tc_gemm<0>, cudaFuncAttributeMaxDynamicSharedMemorySize, GSMEM);
    cudaFuncSetAttribute(tc_gemm<1>, cudaFuncAttributeMaxDynamicSharedMemorySize, GSMEM);
    cudaFuncSetAttribute(tc_gemm<2>, cudaFuncAttributeMaxDynamicSharedMemorySize, GSMEM);
    cudaFuncSetAttribute(tc_gemm<3>, cudaFuncAttributeMaxDynamicSharedMemorySize, GSMEM);

    auto cvt = [&](const float* src, __half* dst, size_t n) {
        cvt_kernel<<<(unsigned)((n/4 + 255) / 256), 256>>>(src, dst, n);
    };

    // zero the exp-rowsum accumulator (graph-capturable memset node)
    cudaMemsetAsync(zrp, 0, sizeof(float) * (size_t)B_ * NH_ * S_);

    // 1) QKV projection; epilogue packs Q/K fp16 per head, writes V fp32 only
    cvt(x, ah, (size_t)BS_ * D_);
    cvt(mha_in_w, bh, (size_t)TD_ * D_);
    tc_gemm<0><<<dim3(TD_/128, BS_/128, 1), 256, GSMEM>>>(
        ah, 0, bh, 0, qkvp, TD_, 0, nullptr,
        mha_in_b, nullptr, D_, nullptr, qh, kh, nullptr);

    // 2) attention scores -> fp16 + fused exp-rowsum; colsum; ctx mean
    tc_gemm<3><<<dim3(S_/128, S_/128, B_*NH_), 256, GSMEM>>>(
        qh, (long)S_*HD_, kh, (long)S_*HD_, nullptr, S_, (long)S_*S_, sc16,
        nullptr, nullptr, HD_, mask, nullptr, nullptr, zrp);
    colsum_kernel<<<dim3(B_*NH_, 2), 256>>>();
    ctxmean_kernel<<<B_*NH_, 192>>>();

    // 3) embedding path
    idx_kernel<<<B_, 256>>>(mask);
    embed_kernel<<<B_, 256>>>(mha_out_w, mha_out_b, asp_w, asp_b, opi_w, opi_b,
                              ia_w, ia_b, io_w, io_b, out);

    // 4) x passthrough
    cudaMemcpyAsync(out + O_X, x, sizeof(float) * (size_t)BS_ * D_, cudaMemcpyDeviceToDevice);

    // 5) build se1/se2 (fp32 + fused fp16 A operands)
    build_se_kernel<<<BS_, 256>>>(x, ah, ah2);

    // 6) decoder stacks on tensor cores
    struct Stack { float* h; __half* a16; const float *iw, *ib, *ow, *ob, *g, *bt; size_t oSE; }
    stacks[2] = {
        { h1, ah,  fwd_iw, fwd_ib, fwd_ow, fwd_ob, fwd_g, fwd_bt, O_SE1 },
        { h2, ah2, rev_iw, rev_ib, rev_ow, rev_ob, rev_g, rev_bt, O_SE2 },
    };
    for (int s = 0; s < 2; s++) {
        Stack& st = stacks[s];
        for (int l = 0; l < NL_; l++) {
            cvt(st.iw + (size_t)l*DFF_*D_, bh, (size_t)DFF_*D_);
            tc_gemm<1><<<dim3(DFF_/128, BS_/128, 1), 256, GSMEM>>>(
                st.a16, 0, bh, 0, nullptr, DFF_, 0, ih,
                st.ib + (size_t)l*DFF_, nullptr, D_, nullptr, nullptr, nullptr, nullptr);
            cvt(st.ow + (size_t)l*D_*DFF_, bh, (size_t)D_*DFF_);
            tc_gemm<2><<<dim3(D_/128, BS_/128, 1), 256, GSMEM>>>(
                ih, 0, bh, 0, tmp, D_, 0, nullptr,
                st.ob + (size_t)l*D_, st.h, DFF_, nullptr, nullptr, nullptr, nullptr);
            bool last = (l == NL_-1);
            float* lnout = last ? (out + st.oSE) : st.h;
            ln_kernel<<<BS_, 256>>>(tmp, st.g + (size_t)l*D_, st.bt + (size_t)l*D_,
                                    lnout, last ? nullptr : st.a16);
        }
    }

    // 7) classifier logits
    logits_kernel<<<BS_, 256>>>(out + O_SE1, cls_a_w, cls_a_b, out + O_LA);
    logits_kernel<<<BS_, 256>>>(out + O_SE2, cls_o_w, cls_o_b, out + O_LO);
}

// round 16
// speedup vs baseline: 1.0520x; 1.0082x over previous
#include <cuda_runtime.h>
#include <cuda_fp16.h>
#include <mma.h>
#include <math.h>
#include <stdint.h>

using namespace nvcuda;

#define B_   16
#define S_   1024
#define D_   768
#define NH_  4
#define HD_  192
#define DFF_ 3072
#define NL_  2
#define C_   3
#define BS_  (B_*S_)     // 16384
#define TD_  (3*D_)      // 2304

// ---- output layout (floats) ----
#define O_LA  ((size_t)0)
#define O_LO  ((size_t)49152)
#define O_X   ((size_t)98304)
#define O_SE1 ((size_t)12681216)
#define O_SE2 ((size_t)25264128)
#define O_IA  ((size_t)37847040)
#define O_IO  ((size_t)37847072)
#define O_E1  ((size_t)37847104)
#define O_E2  ((size_t)37859392)

// ---- scratch (device globals) ----
__device__ float g_qkv[(size_t)BS_*TD_];               // only V third used
__device__ __half g_scores16[(size_t)B_*NH_*S_*S_];    // fp16 scores (pre-scaled)
__device__ float g_zr[B_*NH_*S_];                      // 1/rowsum(exp(s))
__device__ float g_w[B_*NH_*S_];
__device__ float g_ctxmean[B_*D_];
__device__ float g_e1[B_*D_];
__device__ float g_e2[B_*D_];
__device__ int   g_idx[B_];
__device__ float g_h1[(size_t)BS_*D_];
__device__ float g_h2[(size_t)BS_*D_];
__device__ float g_tmp[(size_t)BS_*D_];

// fp16 operand buffers
__device__ __half g_ah[(size_t)BS_*D_];
__device__ __half g_ah2[(size_t)BS_*D_];
__device__ __half g_ih[(size_t)BS_*DFF_];
__device__ __half g_bh[(size_t)DFF_*D_];
__device__ __half g_qh[(size_t)B_*NH_*S_*HD_];
__device__ __half g_kh[(size_t)B_*NH_*S_*HD_];

// ============================================================
__device__ __forceinline__ uint32_t smem_u32(const void* p) {
    uint32_t a;
    asm("{ .reg .u64 t; cvta.to.shared.u64 t, %1; cvt.u32.u64 %0, t; }" : "=r"(a) : "l"(p));
    return a;
}
__device__ __forceinline__ void cp16(uint32_t dst, const void* src) {
    asm volatile("cp.async.cg.shared.global [%0], [%1], 16;" :: "r"(dst), "l"(src));
}
#define CP_COMMIT() asm volatile("cp.async.commit_group;" ::: "memory")
#define CP_WAIT0()  asm volatile("cp.async.wait_group 0;" ::: "memory")
#define CP_WAIT1()  asm volatile("cp.async.wait_group 1;" ::: "memory")

// ============================================================
// fp16 tensor-core GEMM via wmma. (R11 mainloop.)
// EPI: 0 = bias; pack Q(*scale)/K fp16 per head; fp32 C only for V cols
//      1 = bias + exact GELU -> fp16 Ch
//      2 = raw accumulator -> fp32 C direct fragment store (bias+resid in LN)
//      3 = mask -> fp16 Ch (scores; Q pre-scaled; masked = -65504)
// ============================================================
#define SROW   72
#define MATB   18432
#define STAGEB 36864
#define GSMEM  73728   // 2 stages; epilogue: 64KB sf + mask cache above

template<int EPI>
__global__ void __launch_bounds__(256, 2) tc_gemm(
    const __half* __restrict__ A, long aBatch,
    const __half* __restrict__ Bw, long bBatch,
    float* __restrict__ C, int ldc, long cBatch,
    __half* __restrict__ Ch,
    const float* __restrict__ bias, const float* __restrict__ resid,
    int K, const int* __restrict__ mask,
    __half* __restrict__ qh, __half* __restrict__ kh)
{
    extern __shared__ char smem[];
    __half* sbf = (__half*)smem;
    float* sf = (float*)smem;
    const uint32_t sb = smem_u32(smem);
    const int tid = threadIdx.x;
    const int wid = tid >> 5;
    const int wm = wid >> 1;       // 0..3
    const int wn = wid & 1;        // 0..1
    const int m0 = blockIdx.y * 128;
    const int n0 = blockIdx.x * 128;
    const int z  = blockIdx.z;

    A  += (size_t)z * aBatch;
    Bw += (size_t)z * bBatch;
    if (C)  C  += (size_t)z * cBatch;
    if (EPI == 3 && Ch) Ch += (size_t)z * cBatch;

    wmma::fragment<wmma::accumulator, 16, 16, 16, float> acc[2][4];
#pragma unroll
    for (int i = 0; i < 2; i++)
#pragma unroll
        for (int j = 0; j < 4; j++) wmma::fill_fragment(acc[i][j], 0.0f);

    const int nk = K >> 6;

    auto load_stage = [&](int st, int k0) {
        uint32_t base = sb + st * STAGEB;
#pragma unroll
        for (int v = tid; v < 2048; v += 256) {
            int mat = v >> 10;
            int rem = v & 1023;
            int r = rem >> 3, cg = rem & 7;
            uint32_t so = mat * MATB + r * 144 + cg * 16;
            const __half* src = mat ? (Bw + (size_t)(n0 + r) * K + k0 + cg * 8)
                                    : (A  + (size_t)(m0 + r) * K + k0 + cg * 8);
            cp16(base + so, src);
        }
    };

    load_stage(0, 0);
    CP_COMMIT();

    for (int c = 0; c < nk; c++) {
        const int st = c & 1;
        if (c + 1 < nk) {
            load_stage(st ^ 1, (c + 1) << 6);
            CP_COMMIT();
            CP_WAIT1();
        } else {
            CP_WAIT0();
        }
        __syncthreads();

        const __half* As = sbf + st * (STAGEB/2);
        const __half* Bs = As + MATB/2;

#pragma unroll
        for (int kst = 0; kst < 4; kst++) {
            wmma::fragment<wmma::matrix_a, 16, 16, 16, __half, wmma::row_major> fa[2];
#pragma unroll
            for (int i = 0; i < 2; i++)
                wmma::load_matrix_sync(fa[i], As + (wm*32 + i*16) * SROW + kst * 16, SROW);
#pragma unroll
            for (int j = 0; j < 4; j++) {
                wmma::fragment<wmma::matrix_b, 16, 16, 16, __half, wmma::col_major> fb;
                wmma::load_matrix_sync(fb, Bs + (wn*64 + j*16) * SROW + kst * 16, SROW);
#pragma unroll
                for (int i = 0; i < 2; i++)
                    wmma::mma_sync(acc[i][j], fa[i], fb, acc[i][j]);
            }
        }
        __syncthreads();
    }

    // ---- EPI2: direct fragment -> global fp32 store (bias+resid applied in LN) ----
    if (EPI == 2) {
#pragma unroll
        for (int i = 0; i < 2; i++)
#pragma unroll
            for (int j = 0; j < 4; j++)
                wmma::store_matrix_sync(
                    C + (size_t)(m0 + wm*32 + i*16) * ldc + n0 + wn*64 + j*16,
                    acc[i][j], ldc, wmma::mem_row_major);
        return;
    }

    // stage accumulators to smem (first 64KB)
#pragma unroll
    for (int i = 0; i < 2; i++)
#pragma unroll
        for (int j = 0; j < 4; j++)
            wmma::store_matrix_sync(sf + (wm*32 + i*16) * 128 + wn*64 + j*16,
                                    acc[i][j], 128, wmma::mem_row_major);

    // mask cache for EPI3 (above sf region)
    int* maskc = (int*)(smem + 65536);
    if (EPI == 3 && tid < 128) {
        const int b_ = z >> 2;
        maskc[tid] = mask[b_ * S_ + n0 + tid];
    }
    __syncthreads();

    // ---- epilogue: 64 elements per thread, coalesced over columns ----
#pragma unroll 4
    for (int it = 0; it < 64; it++) {
        const int idx = it * 256 + tid;
        const int r = idx >> 7;
        const int cc = idx & 127;
        const int row = m0 + r;
        const int col = n0 + cc;
        float v = sf[idx];
        if (EPI == 0) {
            v += bias[col];
            if (col >= 2 * D_) {
                C[(size_t)row * ldc + col] = v;   // only V third consumed later
            } else {
                int b_ = row >> 10, s_ = row & 1023;
                int c2 = (col < D_) ? col : (col - D_);
                int zz = b_ * NH_ + c2 / HD_;
                size_t po = (size_t)zz * (S_*HD_) + (size_t)s_ * HD_ + (c2 % HD_);
                if (col < D_) qh[po] = __float2half(v * 0.07216878364870322f);
                else          kh[po] = __float2half(v);
            }
        } else if (EPI == 1) {
            v += bias[col];
            v = 0.5f * v * (1.0f + erff(v * 0.70710678118654752f));
            Ch[(size_t)row * ldc + col] = __float2half(v);
        } else {
            if (maskc[cc] == 0) v = -65504.0f;
            Ch[(size_t)row * ldc + col] = __float2half(v);
        }
    }
}

// ============================================================
// fp32 -> fp16
__global__ void cvt_kernel(const float* __restrict__ in,
                           __half* __restrict__ o, size_t n)
{
    size_t i = ((size_t)blockIdx.x * blockDim.x + threadIdx.x) * 4;
    if (i >= n) return;
    float4 v = *(const float4*)(in + i);
    *(__half2*)(o + i)     = __floats2half2_rn(v.x, v.y);
    *(__half2*)(o + i + 2) = __floats2half2_rn(v.z, v.w);
}

// 1/rowsum(exp(s)) per score row. Row has S_=1024 halves: 4 values/thread.
__global__ void zsum_kernel()
{
    const int row = blockIdx.x;
    const int tid = threadIdx.x;
    const __half* r = g_scores16 + (size_t)row * S_;
    float se = 0.f;
#pragma unroll
    for (int i = 0; i < 2; i++) {
        __half2 h = *(const __half2*)(r + tid*2 + i*512);
        float2 f = __half22float2(h);
        se += __expf(f.x) + __expf(f.y);
    }
    __shared__ float red[256];
    red[tid] = se; __syncthreads();
    for (int st = 128; st > 0; st >>= 1) { if (tid < st) red[tid] += red[tid+st]; __syncthreads(); }
    if (tid == 0) g_zr[row] = 1.0f / red[0];
}

// w[z,k] = sum_q exp(s[q,k]) * zr_q — 2 cols per thread via half2
__global__ void colsum_kernel()
{
    const int zz = blockIdx.x;
    const int col2 = blockIdx.y * 512 + threadIdx.x * 2;
    __shared__ float sz[S_];
    for (int q = threadIdx.x; q < S_; q += 256) sz[q] = g_zr[zz*S_+q];
    __syncthreads();
    float a0 = 0.f, a1 = 0.f;
    const __half* sc = g_scores16 + (size_t)zz * S_ * S_ + col2;
    for (int q = 0; q < S_; q++) {
        __half2 h = *(const __half2*)(sc + (size_t)q * S_);
        float2 f = __half22float2(h);
        float rz = sz[q];
        a0 += __expf(f.x) * rz;
        a1 += __expf(f.y) * rz;
    }
    g_w[zz*S_ + col2]     = a0;
    g_w[zz*S_ + col2 + 1] = a1;
}

__global__ void ctxmean_kernel()
{
    const int z = blockIdx.x;
    const int b = z >> 2, h = z & 3;
    const int d = threadIdx.x;
    __shared__ float w[S_];
    for (int k = d; k < S_; k += 192) w[k] = g_w[z*S_+k];
    __syncthreads();
    float acc = 0.f;
    const float* vb = g_qkv + (size_t)b * S_ * TD_ + 2*D_ + h*HD_ + d;
    for (int k = 0; k < S_; k++) acc += w[k] * vb[(size_t)k * TD_];
    g_ctxmean[b*D_ + h*HD_ + d] = acc * (1.0f / S_);
}

__global__ void idx_kernel(const int* __restrict__ mask)
{
    const int b = blockIdx.x, tid = threadIdx.x;
    __shared__ int red[256];
    int s = 0;
    for (int k = tid; k < S_; k += 256) s += mask[b*S_ + k];
    red[tid] = s; __syncthreads();
    for (int st = 128; st > 0; st >>= 1) { if (tid < st) red[tid] += red[tid+st]; __syncthreads(); }
    if (tid == 0) g_idx[b] = red[0] - 1;
}

__global__ void embed_kernel(
    const float* __restrict__ Wout, const float* __restrict__ bout,
    const float* __restrict__ Wasp, const float* __restrict__ basp,
    const float* __restrict__ Wopi, const float* __restrict__ bopi,
    const float* __restrict__ Wia,  const float* __restrict__ bia,
    const float* __restrict__ Wio,  const float* __restrict__ bio,
    float* __restrict__ out)
{
    const int b = blockIdx.x, tid = threadIdx.x;
    __shared__ float cm[D_], emb[D_], e1s[D_], e2s[D_];
    for (int d = tid; d < D_; d += 256) cm[d] = g_ctxmean[b*D_ + d];
    __syncthreads();
    for (int n = tid; n < D_; n += 256) {
        float a = bout[n];
        const float* wr = Wout + (size_t)n * D_;
        for (int d = 0; d < D_; d++) a += cm[d] * wr[d];
        emb[n] = a;
    }
    __syncthreads();
    for (int n = tid; n < D_; n += 256) {
        float a = basp[n], o = bopi[n];
        const float* wa = Wasp + (size_t)n * D_;
        const float* wo = Wopi + (size_t)n * D_;
        for (int d = 0; d < D_; d++) { a += emb[d] * wa[d]; o += emb[d] * wo[d]; }
        e1s[n] = a; e2s[n] = o;
    }
    __syncthreads();
    for (int d = tid; d < D_; d += 256) {
        g_e1[b*D_ + d] = e1s[d];
        g_e2[b*D_ + d] = e2s[d];
        out[O_E1 + (size_t)b*D_ + d] = e1s[d];
        out[O_E2 + (size_t)b*D_ + d] = e2s[d];
    }
    if (tid < 2) {
        float a = bia[tid];
        const float* w = Wia + (size_t)tid * D_;
        for (int d = 0; d < D_; d++) a += e1s[d] * w[d];
        out[O_IA + b*2 + tid] = a;
    } else if (tid < 4) {
        int c = tid - 2;
        float a = bio[c];
        const float* w = Wio + (size_t)c * D_;
        for (int d = 0; d < D_; d++) a += e2s[d] * w[d];
        out[O_IO + b*2 + c] = a;
    }
}

// build se1/se2: fp32 h buffers + fp16 A operands for first decoder GEMM
__global__ void build_se_kernel(const float* __restrict__ x,
                                __half* __restrict__ oh1, __half* __restrict__ oh2)
{
    const int blk = blockIdx.x;
    const int b = blk >> 10, s = blk & 1023;
    const int idx = g_idx[b];
#pragma unroll
    for (int i = 0; i < 3; i++) {
        int d = threadIdx.x + i * 256;
        float xv = x[(size_t)blk * D_ + d];
        float e1v = g_e1[b*D_ + d], e2v = g_e2[b*D_ + d];
        float v1 = (s == idx) ? e2v : ((s == 0) ? e1v : xv);
        float v2 = (s == 0) ? e1v : ((s == idx) ? e2v : xv);
        size_t o = (size_t)blk * D_ + d;
        g_h1[o] = v1;
        g_h2[o] = v2;
        oh1[o] = __float2half(v1);
        oh2[o] = __float2half(v2);
    }
}

// layernorm over (gemm_out + bias + resid); fp32 out (+ optional fp16 out)
__global__ void ln_kernel(const float* __restrict__ in,
                          const float* __restrict__ bias, const float* __restrict__ resid,
                          const float* __restrict__ g, const float* __restrict__ bt,
                          float* __restrict__ outp, __half* __restrict__ oh)
{
    const int row = blockIdx.x, tid = threadIdx.x;
    const float* r = in + (size_t)row * D_;
    const float* h = resid + (size_t)row * D_;
    float v0 = r[tid]     + bias[tid]     + h[tid];
    float v1 = r[tid+256] + bias[tid+256] + h[tid+256];
    float v2 = r[tid+512] + bias[tid+512] + h[tid+512];
    __shared__ float red[256];
    red[tid] = v0 + v1 + v2; __syncthreads();
    for (int st = 128; st > 0; st >>= 1) { if (tid < st) red[tid] += red[tid+st]; __syncthreads(); }
    float mean = red[0] * (1.0f / D_);
    __syncthreads();
    float d0 = v0 - mean, d1 = v1 - mean, d2 = v2 - mean;
    red[tid] = d0*d0 + d1*d1 + d2*d2; __syncthreads();
    for (int st = 128; st > 0; st >>= 1) { if (tid < st) red[tid] += red[tid+st]; __syncthreads(); }
    float rstd = rsqrtf(red[0] * (1.0f / D_) + 1e-12f);
    float o0 = d0 * rstd * g[tid]     + bt[tid];
    float o1 = d1 * rstd * g[tid+256] + bt[tid+256];
    float o2 = d2 * rstd * g[tid+512] + bt[tid+512];
    float* o = outp + (size_t)row * D_;
    o[tid] = o0; o[tid+256] = o1; o[tid+512] = o2;
    if (oh) {
        size_t base = (size_t)row * D_;
        oh[base+tid]     = __float2half(o0);
        oh[base+tid+256] = __float2half(o1);
        oh[base+tid+512] = __float2half(o2);
    }
}

__global__ void logits_kernel(const float* __restrict__ in, const float* __restrict__ W,
                              const float* __restrict__ bias, float* __restrict__ outp)
{
    const int row = blockIdx.x, tid = threadIdx.x;
    __shared__ float srow[D_];
    const float* r = in + (size_t)row * D_;
    srow[tid] = r[tid]; srow[tid+256] = r[tid+256]; srow[tid+512] = r[tid+512];
    __syncthreads();
    float a0 = 0.f, a1 = 0.f, a2 = 0.f;
    for (int d = tid; d < D_; d += 256) {
        float x = srow[d];
        a0 += x * W[d]; a1 += x * W[D_ + d]; a2 += x * W[2*D_ + d];
    }
    __shared__ float red[3][256];
    red[0][tid] = a0; red[1][tid] = a1; red[2][tid] = a2;
    __syncthreads();
    for (int st = 128; st > 0; st >>= 1) {
        if (tid < st) {
            red[0][tid] += red[0][tid+st];
            red[1][tid] += red[1][tid+st];
            red[2][tid] += red[2][tid+st];
        }
        __syncthreads();
    }
    if (tid < 3) outp[(size_t)row * C_ + tid] = red[tid][0] + bias[tid];
}

// ============================================================
extern "C" void kernel_launch(void* const* d_in, const int* in_sizes, int n_in,
                              void* d_out, int out_size)
{
    const float* x        = (const float*)d_in[0];
    const int*   mask     = (const int*)  d_in[1];
    const float* mha_in_w = (const float*)d_in[2];
    const float* mha_in_b = (const float*)d_in[3];
    const float* mha_out_w= (const float*)d_in[4];
    const float* mha_out_b= (const float*)d_in[5];
    const float* asp_w    = (const float*)d_in[6];
    const float* asp_b    = (const float*)d_in[7];
    const float* opi_w    = (const float*)d_in[8];
    const float* opi_b    = (const float*)d_in[9];
    const float* ia_w     = (const float*)d_in[10];
    const float* ia_b     = (const float*)d_in[11];
    const float* io_w     = (const float*)d_in[12];
    const float* io_b     = (const float*)d_in[13];
    const float* fwd_iw   = (const float*)d_in[14];
    const float* fwd_ib   = (const float*)d_in[15];
    const float* fwd_ow   = (const float*)d_in[16];
    const float* fwd_ob   = (const float*)d_in[17];
    const float* fwd_g    = (const float*)d_in[18];
    const float* fwd_bt   = (const float*)d_in[19];
    const float* rev_iw   = (const float*)d_in[20];
    const float* rev_ib   = (const float*)d_in[21];
    const float* rev_ow   = (const float*)d_in[22];
    const float* rev_ob   = (const float*)d_in[23];
    const float* rev_g    = (const float*)d_in[24];
    const float* rev_bt   = (const float*)d_in[25];
    const float* cls_a_w  = (const float*)d_in[26];
    const float* cls_a_b  = (const float*)d_in[27];
    const float* cls_o_w  = (const float*)d_in[28];
    const float* cls_o_b  = (const float*)d_in[29];
    float* out = (float*)d_out;

    float *qkvp, *h1, *h2, *tmp;
    __half *ah, *ah2, *ih, *bh, *qh, *kh, *sc16;
    cudaGetSymbolAddress((void**)&qkvp, g_qkv);
    cudaGetSymbolAddress((void**)&sc16, g_scores16);
    cudaGetSymbolAddress((void**)&h1,   g_h1);
    cudaGetSymbolAddress((void**)&h2,   g_h2);
    cudaGetSymbolAddress((void**)&tmp,  g_tmp);
    cudaGetSymbolAddress((void**)&ah,   g_ah);
    cudaGetSymbolAddress((void**)&ah2,  g_ah2);
    cudaGetSymbolAddress((void**)&ih,   g_ih);
    cudaGetSymbolAddress((void**)&bh,   g_bh);
    cudaGetSymbolAddress((void**)&qh,   g_qh);
    cudaGetSymbolAddress((void**)&kh,   g_kh);

    cudaFuncSetAttribute(tc_gemm<0>, cudaFuncAttributeMaxDynamicSharedMemorySize, GSMEM);
    cudaFuncSetAttribute(tc_gemm<1>, cudaFuncAttributeMaxDynamicSharedMemorySize, GSMEM);
    cudaFuncSetAttribute(tc_gemm<2>, cudaFuncAttributeMaxDynamicSharedMemorySize, GSMEM);
    cudaFuncSetAttribute(tc_gemm<3>, cudaFuncAttributeMaxDynamicSharedMemorySize, GSMEM);

    auto cvt = [&](const float* src, __half* dst, size_t n) {
        cvt_kernel<<<(unsigned)((n/4 + 255) / 256), 256>>>(src, dst, n);
    };

    // 1) QKV projection; epilogue packs Q(*scale)/K fp16 per head, writes V fp32 only
    cvt(x, ah, (size_t)BS_ * D_);
    cvt(mha_in_w, bh, (size_t)TD_ * D_);
    tc_gemm<0><<<dim3(TD_/128, BS_/128, 1), 256, GSMEM>>>(
        ah, 0, bh, 0, qkvp, TD_, 0, nullptr,
        mha_in_b, nullptr, D_, nullptr, qh, kh);

    // 2) attention scores -> fp16; zsum; colsum; ctx mean
    tc_gemm<3><<<dim3(S_/128, S_/128, B_*NH_), 256, GSMEM>>>(
        qh, (long)S_*HD_, kh, (long)S_*HD_, nullptr, S_, (long)S_*S_, sc16,
        nullptr, nullptr, HD_, mask, nullptr, nullptr);
    zsum_kernel<<<B_*NH_*S_, 256>>>();
    colsum_kernel<<<dim3(B_*NH_, 2), 256>>>();
    ctxmean_kernel<<<B_*NH_, 192>>>();

    // 3) embedding path
    idx_kernel<<<B_, 256>>>(mask);
    embed_kernel<<<B_, 256>>>(mha_out_w, mha_out_b, asp_w, asp_b, opi_w, opi_b,
                              ia_w, ia_b, io_w, io_b, out);

    // 4) x passthrough
    cudaMemcpyAsync(out + O_X, x, sizeof(float) * (size_t)BS_ * D_, cudaMemcpyDeviceToDevice);

    // 5) build se1/se2 (fp32 + fused fp16 A operands)
    build_se_kernel<<<BS_, 256>>>(x, ah, ah2);

    // 6) decoder stacks on tensor cores
    struct Stack { float* h; __half* a16; const float *iw, *ib, *ow, *ob, *g, *bt; size_t oSE; }
    stacks[2] = {
        { h1, ah,  fwd_iw, fwd_ib, fwd_ow, fwd_ob, fwd_g, fwd_bt, O_SE1 },
        { h2, ah2, rev_iw, rev_ib, rev_ow, rev_ob, rev_g, rev_bt, O_SE2 },
    };
    for (int s = 0; s < 2; s++) {
        Stack& st = stacks[s];
        for (int l = 0; l < NL_; l++) {
            cvt(st.iw + (size_t)l*DFF_*D_, bh, (size_t)DFF_*D_);
            tc_gemm<1><<<dim3(DFF_/128, BS_/128, 1), 256, GSMEM>>>(
                st.a16, 0, bh, 0, nullptr, DFF_, 0, ih,
                st.ib + (size_t)l*DFF_, nullptr, D_, nullptr, nullptr, nullptr);
            cvt(st.ow + (size_t)l*D_*DFF_, bh, (size_t)D_*DFF_);
            tc_gemm<2><<<dim3(D_/128, BS_/128, 1), 256, GSMEM>>>(
                ih, 0, bh, 0, tmp, D_, 0, nullptr,
                nullptr, nullptr, DFF_, nullptr, nullptr, nullptr);
            bool last = (l == NL_-1);
            float* lnout = last ? (out + st.oSE) : st.h;
            ln_kernel<<<BS_, 256>>>(tmp, st.ob + (size_t)l*D_, st.h,
                                    st.g + (size_t)l*D_, st.bt + (size_t)l*D_,
                                    lnout, last ? nullptr : st.a16);
        }
    }

    // 7) classifier logits
    logits_kernel<<<BS_, 256>>>(out + O_SE1, cls_a_w, cls_a_b, out + O_LA);
    logits_kernel<<<BS_, 256>>>(out + O_SE2, cls_o_w, cls_o_b, out + O_LO);
}

// round 17
// speedup vs baseline: 1.1700x; 1.1121x over previous
#include <cuda_runtime.h>
#include <cuda_fp16.h>
#include <mma.h>
#include <math.h>
#include <stdint.h>

using namespace nvcuda;

#define B_   16
#define S_   1024
#define D_   768
#define NH_  4
#define HD_  192
#define DFF_ 3072
#define NL_  2
#define C_   3
#define BS_  (B_*S_)     // 16384
#define TD_  (3*D_)      // 2304

// ---- output layout (floats) ----
#define O_LA  ((size_t)0)
#define O_LO  ((size_t)49152)
#define O_X   ((size_t)98304)
#define O_SE1 ((size_t)12681216)
#define O_SE2 ((size_t)25264128)   // = O_SE1 + BS_*D_ (contiguous)
#define O_IA  ((size_t)37847040)
#define O_IO  ((size_t)37847072)
#define O_E1  ((size_t)37847104)
#define O_E2  ((size_t)37859392)

// ---- scratch (device globals) ----
__device__ float g_qkv[(size_t)BS_*TD_];               // only V third used
__device__ __half g_scores16[(size_t)B_*NH_*S_*S_];    // fp16 scores (pre-scaled)
__device__ float g_zr[B_*NH_*S_];                      // 1/rowsum(exp(s))
__device__ float g_w[B_*NH_*S_];
__device__ float g_ctxmean[B_*D_];
__device__ float g_e1[B_*D_];
__device__ float g_e2[B_*D_];
__device__ int   g_idx[B_];

// batched (stack-contiguous) decoder buffers
__device__ float  g_hh[(size_t)2*BS_*D_];              // fp32 h (resid), both stacks
__device__ float  g_t2[(size_t)2*BS_*D_];              // gemm2 raw out
__device__ __half g_a2[(size_t)2*BS_*D_];              // fp16 A operands
__device__ __half g_i2[(size_t)2*BS_*DFF_];            // fp16 intermediate
__device__ __half g_b2[(size_t)2*DFF_*D_];             // fp16 weights (both stacks)
__device__ __half g_qh[(size_t)B_*NH_*S_*HD_];
__device__ __half g_kh[(size_t)B_*NH_*S_*HD_];

// ============================================================
__device__ __forceinline__ uint32_t smem_u32(const void* p) {
    uint32_t a;
    asm("{ .reg .u64 t; cvta.to.shared.u64 t, %1; cvt.u32.u64 %0, t; }" : "=r"(a) : "l"(p));
    return a;
}
__device__ __forceinline__ void cp16(uint32_t dst, const void* src) {
    asm volatile("cp.async.cg.shared.global [%0], [%1], 16;" :: "r"(dst), "l"(src));
}
#define CP_COMMIT() asm volatile("cp.async.commit_group;" ::: "memory")
#define CP_WAIT0()  asm volatile("cp.async.wait_group 0;" ::: "memory")
#define CP_WAIT1()  asm volatile("cp.async.wait_group 1;" ::: "memory")

// ============================================================
// fp16 tensor-core GEMM via wmma. (R11 mainloop.)
// EPI: 0 = bias; pack Q(*scale)/K fp16 per head; fp32 C only for V cols
//      1 = bias(z-select) + exact GELU -> fp16 Ch (batched z)
//      2 = raw accumulator -> fp32 C direct fragment store (batched z)
//      3 = mask -> fp16 Ch (scores; Q pre-scaled; masked = -65504)
// ============================================================
#define SROW   72
#define MATB   18432
#define STAGEB 36864
#define GSMEM  73728   // 2 stages; epilogue: 64KB sf + mask cache above

template<int EPI>
__global__ void __launch_bounds__(256, 2) tc_gemm(
    const __half* __restrict__ A, long aBatch,
    const __half* __restrict__ Bw, long bBatch,
    float* __restrict__ C, int ldc, long cBatch,
    __half* __restrict__ Ch,
    const float* __restrict__ bias, const float* __restrict__ bias2,
    int K, const int* __restrict__ mask,
    __half* __restrict__ qh, __half* __restrict__ kh)
{
    extern __shared__ char smem[];
    __half* sbf = (__half*)smem;
    float* sf = (float*)smem;
    const uint32_t sb = smem_u32(smem);
    const int tid = threadIdx.x;
    const int wid = tid >> 5;
    const int wm = wid >> 1;       // 0..3
    const int wn = wid & 1;        // 0..1
    const int m0 = blockIdx.y * 128;
    const int n0 = blockIdx.x * 128;
    const int z  = blockIdx.z;

    A  += (size_t)z * aBatch;
    Bw += (size_t)z * bBatch;
    if (C)  C  += (size_t)z * cBatch;
    if ((EPI == 3 || EPI == 1) && Ch) Ch += (size_t)z * cBatch;
    const float* bb = (EPI == 1 && z == 1) ? bias2 : bias;

    wmma::fragment<wmma::accumulator, 16, 16, 16, float> acc[2][4];
#pragma unroll
    for (int i = 0; i < 2; i++)
#pragma unroll
        for (int j = 0; j < 4; j++) wmma::fill_fragment(acc[i][j], 0.0f);

    const int nk = K >> 6;

    auto load_stage = [&](int st, int k0) {
        uint32_t base = sb + st * STAGEB;
#pragma unroll
        for (int v = tid; v < 2048; v += 256) {
            int mat = v >> 10;
            int rem = v & 1023;
            int r = rem >> 3, cg = rem & 7;
            uint32_t so = mat * MATB + r * 144 + cg * 16;
            const __half* src = mat ? (Bw + (size_t)(n0 + r) * K + k0 + cg * 8)
                                    : (A  + (size_t)(m0 + r) * K + k0 + cg * 8);
            cp16(base + so, src);
        }
    };

    load_stage(0, 0);
    CP_COMMIT();

    for (int c = 0; c < nk; c++) {
        const int st = c & 1;
        if (c + 1 < nk) {
            load_stage(st ^ 1, (c + 1) << 6);
            CP_COMMIT();
            CP_WAIT1();
        } else {
            CP_WAIT0();
        }
        __syncthreads();

        const __half* As = sbf + st * (STAGEB/2);
        const __half* Bs = As + MATB/2;

#pragma unroll
        for (int kst = 0; kst < 4; kst++) {
            wmma::fragment<wmma::matrix_a, 16, 16, 16, __half, wmma::row_major> fa[2];
#pragma unroll
            for (int i = 0; i < 2; i++)
                wmma::load_matrix_sync(fa[i], As + (wm*32 + i*16) * SROW + kst * 16, SROW);
#pragma unroll
            for (int j = 0; j < 4; j++) {
                wmma::fragment<wmma::matrix_b, 16, 16, 16, __half, wmma::col_major> fb;
                wmma::load_matrix_sync(fb, Bs + (wn*64 + j*16) * SROW + kst * 16, SROW);
#pragma unroll
                for (int i = 0; i < 2; i++)
                    wmma::mma_sync(acc[i][j], fa[i], fb, acc[i][j]);
            }
        }
        __syncthreads();
    }

    // ---- EPI2: direct fragment -> global fp32 store (bias+resid in LN) ----
    if (EPI == 2) {
#pragma unroll
        for (int i = 0; i < 2; i++)
#pragma unroll
            for (int j = 0; j < 4; j++)
                wmma::store_matrix_sync(
                    C + (size_t)(m0 + wm*32 + i*16) * ldc + n0 + wn*64 + j*16,
                    acc[i][j], ldc, wmma::mem_row_major);
        return;
    }

    // stage accumulators to smem (first 64KB)
#pragma unroll
    for (int i = 0; i < 2; i++)
#pragma unroll
        for (int j = 0; j < 4; j++)
            wmma::store_matrix_sync(sf + (wm*32 + i*16) * 128 + wn*64 + j*16,
                                    acc[i][j], 128, wmma::mem_row_major);

    // mask cache for EPI3 (above sf region)
    int* maskc = (int*)(smem + 65536);
    if (EPI == 3 && tid < 128) {
        const int b_ = z >> 2;
        maskc[tid] = mask[b_ * S_ + n0 + tid];
    }
    __syncthreads();

    // ---- epilogue: 64 elements per thread, coalesced over columns ----
#pragma unroll 4
    for (int it = 0; it < 64; it++) {
        const int idx = it * 256 + tid;
        const int r = idx >> 7;
        const int cc = idx & 127;
        const int row = m0 + r;
        const int col = n0 + cc;
        float v = sf[idx];
        if (EPI == 0) {
            v += bb[col];
            if (col >= 2 * D_) {
                C[(size_t)row * ldc + col] = v;   // only V third consumed later
            } else {
                int b_ = row >> 10, s_ = row & 1023;
                int c2 = (col < D_) ? col : (col - D_);
                int zz = b_ * NH_ + c2 / HD_;
                size_t po = (size_t)zz * (S_*HD_) + (size_t)s_ * HD_ + (c2 % HD_);
                if (col < D_) qh[po] = __float2half(v * 0.07216878364870322f);
                else          kh[po] = __float2half(v);
            }
        } else if (EPI == 1) {
            v += bb[col];
            v = 0.5f * v * (1.0f + erff(v * 0.70710678118654752f));
            Ch[(size_t)row * ldc + col] = __float2half(v);
        } else {
            if (maskc[cc] == 0) v = -65504.0f;
            Ch[(size_t)row * ldc + col] = __float2half(v);
        }
    }
}

// ============================================================
// fp32 -> fp16
__global__ void cvt_kernel(const float* __restrict__ in,
                           __half* __restrict__ o, size_t n)
{
    size_t i = ((size_t)blockIdx.x * blockDim.x + threadIdx.x) * 4;
    if (i >= n) return;
    float4 v = *(const float4*)(in + i);
    *(__half2*)(o + i)     = __floats2half2_rn(v.x, v.y);
    *(__half2*)(o + i + 2) = __floats2half2_rn(v.z, v.w);
}

// 1/rowsum(exp(s)) per score row. Row has S_=1024 halves: 4 values/thread.
__global__ void zsum_kernel()
{
    const int row = blockIdx.x;
    const int tid = threadIdx.x;
    const __half* r = g_scores16 + (size_t)row * S_;
    float se = 0.f;
#pragma unroll
    for (int i = 0; i < 2; i++) {
        __half2 h = *(const __half2*)(r + tid*2 + i*512);
        float2 f = __half22float2(h);
        se += __expf(f.x) + __expf(f.y);
    }
    __shared__ float red[256];
    red[tid] = se; __syncthreads();
    for (int st = 128; st > 0; st >>= 1) { if (tid < st) red[tid] += red[tid+st]; __syncthreads(); }
    if (tid == 0) g_zr[row] = 1.0f / red[0];
}

// w[z,k] = sum_q exp(s[q,k]) * zr_q — 2 cols per thread via half2
__global__ void colsum_kernel()
{
    const int zz = blockIdx.x;
    const int col2 = blockIdx.y * 512 + threadIdx.x * 2;
    __shared__ float sz[S_];
    for (int q = threadIdx.x; q < S_; q += 256) sz[q] = g_zr[zz*S_+q];
    __syncthreads();
    float a0 = 0.f, a1 = 0.f;
    const __half* sc = g_scores16 + (size_t)zz * S_ * S_ + col2;
    for (int q = 0; q < S_; q++) {
        __half2 h = *(const __half2*)(sc + (size_t)q * S_);
        float2 f = __half22float2(h);
        float rz = sz[q];
        a0 += __expf(f.x) * rz;
        a1 += __expf(f.y) * rz;
    }
    g_w[zz*S_ + col2]     = a0;
    g_w[zz*S_ + col2 + 1] = a1;
}

// ctx mean, k split in 8 segments of 128; atomicAdd into zeroed ctxmean
__global__ void ctxmean_kernel()
{
    const int z = blockIdx.x;
    const int seg = blockIdx.y;
    const int b = z >> 2, h = z & 3;
    const int d = threadIdx.x;
    __shared__ float w[128];
    if (d < 128) w[d] = g_w[z*S_ + seg*128 + d];
    __syncthreads();
    float acc = 0.f;
    const float* vb = g_qkv + (size_t)b * S_ * TD_ + (size_t)(seg*128) * TD_ + 2*D_ + h*HD_ + d;
#pragma unroll 8
    for (int k = 0; k < 128; k++) acc += w[k] * vb[(size_t)k * TD_];
    atomicAdd(&g_ctxmean[b*D_ + h*HD_ + d], acc * (1.0f / S_));
}

__global__ void idx_kernel(const int* __restrict__ mask)
{
    const int b = blockIdx.x, tid = threadIdx.x;
    __shared__ int red[256];
    int s = 0;
    for (int k = tid; k < S_; k += 256) s += mask[b*S_ + k];
    red[tid] = s; __syncthreads();
    for (int st = 128; st > 0; st >>= 1) { if (tid < st) red[tid] += red[tid+st]; __syncthreads(); }
    if (tid == 0) g_idx[b] = red[0] - 1;
}

__global__ void embed_kernel(
    const float* __restrict__ Wout, const float* __restrict__ bout,
    const float* __restrict__ Wasp, const float* __restrict__ basp,
    const float* __restrict__ Wopi, const float* __restrict__ bopi,
    const float* __restrict__ Wia,  const float* __restrict__ bia,
    const float* __restrict__ Wio,  const float* __restrict__ bio,
    float* __restrict__ out)
{
    const int b = blockIdx.x, tid = threadIdx.x;
    __shared__ float cm[D_], emb[D_], e1s[D_], e2s[D_];
    for (int d = tid; d < D_; d += 256) cm[d] = g_ctxmean[b*D_ + d];
    __syncthreads();
    for (int n = tid; n < D_; n += 256) {
        float a = bout[n];
        const float* wr = Wout + (size_t)n * D_;
        for (int d = 0; d < D_; d++) a += cm[d] * wr[d];
        emb[n] = a;
    }
    __syncthreads();
    for (int n = tid; n < D_; n += 256) {
        float a = basp[n], o = bopi[n];
        const float* wa = Wasp + (size_t)n * D_;
        const float* wo = Wopi + (size_t)n * D_;
        for (int d = 0; d < D_; d++) { a += emb[d] * wa[d]; o += emb[d] * wo[d]; }
        e1s[n] = a; e2s[n] = o;
    }
    __syncthreads();
    for (int d = tid; d < D_; d += 256) {
        g_e1[b*D_ + d] = e1s[d];
        g_e2[b*D_ + d] = e2s[d];
        out[O_E1 + (size_t)b*D_ + d] = e1s[d];
        out[O_E2 + (size_t)b*D_ + d] = e2s[d];
    }
    if (tid < 2) {
        float a = bia[tid];
        const float* w = Wia + (size_t)tid * D_;
        for (int d = 0; d < D_; d++) a += e1s[d] * w[d];
        out[O_IA + b*2 + tid] = a;
    } else if (tid < 4) {
        int c = tid - 2;
        float a = bio[c];
        const float* w = Wio + (size_t)c * D_;
        for (int d = 0; d < D_; d++) a += e2s[d] * w[d];
        out[O_IO + b*2 + c] = a;
    }
}

// build se1/se2 (both stacks into contiguous buffers) + x passthrough
__global__ void build_se_kernel(const float* __restrict__ x, float* __restrict__ out)
{
    const int blk = blockIdx.x;
    const int b = blk >> 10, s = blk & 1023;
    const int idx = g_idx[b];
#pragma unroll
    for (int i = 0; i < 3; i++) {
        int d = threadIdx.x + i * 256;
        float xv = x[(size_t)blk * D_ + d];
        float e1v = g_e1[b*D_ + d], e2v = g_e2[b*D_ + d];
        float v1 = (s == idx) ? e2v : ((s == 0) ? e1v : xv);
        float v2 = (s == 0) ? e1v : ((s == idx) ? e2v : xv);
        size_t o = (size_t)blk * D_ + d;
        out[O_X + o] = xv;
        g_hh[o] = v1;
        g_hh[(size_t)BS_*D_ + o] = v2;
        g_a2[o] = __float2half(v1);
        g_a2[(size_t)BS_*D_ + o] = __float2half(v2);
    }
}

// batched layernorm over (gemm_out + bias + resid); stack s = row >> 14
__global__ void ln_kernel(const float* __restrict__ in,
                          const float* __restrict__ bias0, const float* __restrict__ bias1,
                          const float* __restrict__ g0, const float* __restrict__ g1,
                          const float* __restrict__ bt0, const float* __restrict__ bt1,
                          float* __restrict__ outp, __half* __restrict__ oh)
{
    const int row = blockIdx.x, tid = threadIdx.x;
    const int s = row >> 14;
    const float* bias = s ? bias1 : bias0;
    const float* g    = s ? g1 : g0;
    const float* bt   = s ? bt1 : bt0;
    const float* r = in + (size_t)row * D_;
    const float* h = g_hh + (size_t)row * D_;
    float v0 = r[tid]     + bias[tid]     + h[tid];
    float v1 = r[tid+256] + bias[tid+256] + h[tid+256];
    float v2 = r[tid+512] + bias[tid+512] + h[tid+512];
    __shared__ float red[256];
    red[tid] = v0 + v1 + v2; __syncthreads();
    for (int st = 128; st > 0; st >>= 1) { if (tid < st) red[tid] += red[tid+st]; __syncthreads(); }
    float mean = red[0] * (1.0f / D_);
    __syncthreads();
    float d0 = v0 - mean, d1 = v1 - mean, d2 = v2 - mean;
    red[tid] = d0*d0 + d1*d1 + d2*d2; __syncthreads();
    for (int st = 128; st > 0; st >>= 1) { if (tid < st) red[tid] += red[tid+st]; __syncthreads(); }
    float rstd = rsqrtf(red[0] * (1.0f / D_) + 1e-12f);
    float o0 = d0 * rstd * g[tid]     + bt[tid];
    float o1 = d1 * rstd * g[tid+256] + bt[tid+256];
    float o2 = d2 * rstd * g[tid+512] + bt[tid+512];
    float* o = outp + (size_t)row * D_;
    o[tid] = o0; o[tid+256] = o1; o[tid+512] = o2;
    if (oh) {
        size_t base = (size_t)row * D_;
        oh[base+tid]     = __float2half(o0);
        oh[base+tid+256] = __float2half(o1);
        oh[base+tid+512] = __float2half(o2);
    }
}

// batched logits: rows [0,2*BS), W selected by stack
__global__ void logits_kernel(const float* __restrict__ in,
                              const float* __restrict__ W0, const float* __restrict__ b0,
                              const float* __restrict__ W1, const float* __restrict__ b1,
                              float* __restrict__ outp)
{
    const int row = blockIdx.x, tid = threadIdx.x;
    const int s = row >> 14;
    const float* W = s ? W1 : W0;
    const float* bias = s ? b1 : b0;
    __shared__ float srow[D_];
    const float* r = in + (size_t)row * D_;
    srow[tid] = r[tid]; srow[tid+256] = r[tid+256]; srow[tid+512] = r[tid+512];
    __syncthreads();
    float a0 = 0.f, a1 = 0.f, a2 = 0.f;
    for (int d = tid; d < D_; d += 256) {
        float x = srow[d];
        a0 += x * W[d]; a1 += x * W[D_ + d]; a2 += x * W[2*D_ + d];
    }
    __shared__ float red[3][256];
    red[0][tid] = a0; red[1][tid] = a1; red[2][tid] = a2;
    __syncthreads();
    for (int st = 128; st > 0; st >>= 1) {
        if (tid < st) {
            red[0][tid] += red[0][tid+st];
            red[1][tid] += red[1][tid+st];
            red[2][tid] += red[2][tid+st];
        }
        __syncthreads();
    }
    if (tid < 3) outp[(size_t)row * C_ + tid] = red[tid][0] + bias[tid];
}

// ============================================================
extern "C" void kernel_launch(void* const* d_in, const int* in_sizes, int n_in,
                              void* d_out, int out_size)
{
    const float* x        = (const float*)d_in[0];
    const int*   mask     = (const int*)  d_in[1];
    const float* mha_in_w = (const float*)d_in[2];
    const float* mha_in_b = (const float*)d_in[3];
    const float* mha_out_w= (const float*)d_in[4];
    const float* mha_out_b= (const float*)d_in[5];
    const float* asp_w    = (const float*)d_in[6];
    const float* asp_b    = (const float*)d_in[7];
    const float* opi_w    = (const float*)d_in[8];
    const float* opi_b    = (const float*)d_in[9];
    const float* ia_w     = (const float*)d_in[10];
    const float* ia_b     = (const float*)d_in[11];
    const float* io_w     = (const float*)d_in[12];
    const float* io_b     = (const float*)d_in[13];
    const float* fwd_iw   = (const float*)d_in[14];
    const float* fwd_ib   = (const float*)d_in[15];
    const float* fwd_ow   = (const float*)d_in[16];
    const float* fwd_ob   = (const float*)d_in[17];
    const float* fwd_g    = (const float*)d_in[18];
    const float* fwd_bt   = (const float*)d_in[19];
    const float* rev_iw   = (const float*)d_in[20];
    const float* rev_ib   = (const float*)d_in[21];
    const float* rev_ow   = (const float*)d_in[22];
    const float* rev_ob   = (const float*)d_in[23];
    const float* rev_g    = (const float*)d_in[24];
    const float* rev_bt   = (const float*)d_in[25];
    const float* cls_a_w  = (const float*)d_in[26];
    const float* cls_a_b  = (const float*)d_in[27];
    const float* cls_o_w  = (const float*)d_in[28];
    const float* cls_o_b  = (const float*)d_in[29];
    float* out = (float*)d_out;

    float *qkvp, *t2, *cmp;
    __half *a2, *i2, *b2, *qh, *kh, *sc16;
    cudaGetSymbolAddress((void**)&qkvp, g_qkv);
    cudaGetSymbolAddress((void**)&sc16, g_scores16);
    cudaGetSymbolAddress((void**)&cmp,  g_ctxmean);
    cudaGetSymbolAddress((void**)&t2,   g_t2);
    cudaGetSymbolAddress((void**)&a2,   g_a2);
    cudaGetSymbolAddress((void**)&i2,   g_i2);
    cudaGetSymbolAddress((void**)&b2,   g_b2);
    cudaGetSymbolAddress((void**)&qh,   g_qh);
    cudaGetSymbolAddress((void**)&kh,   g_kh);

    cudaFuncSetAttribute(tc_gemm<0>, cudaFuncAttributeMaxDynamicSharedMemorySize, GSMEM);
    cudaFuncSetAttribute(tc_gemm<1>, cudaFuncAttributeMaxDynamicSharedMemorySize, GSMEM);
    cudaFuncSetAttribute(tc_gemm<2>, cudaFuncAttributeMaxDynamicSharedMemorySize, GSMEM);
    cudaFuncSetAttribute(tc_gemm<3>, cudaFuncAttributeMaxDynamicSharedMemorySize, GSMEM);

    auto cvt = [&](const float* src, __half* dst, size_t n) {
        cvt_kernel<<<(unsigned)((n/4 + 255) / 256), 256>>>(src, dst, n);
    };

    // 1) QKV projection; epilogue packs Q(*scale)/K fp16 per head, writes V fp32 only
    cvt(x, a2, (size_t)BS_ * D_);
    cvt(mha_in_w, b2, (size_t)TD_ * D_);
    tc_gemm<0><<<dim3(TD_/128, BS_/128, 1), 256, GSMEM>>>(
        a2, 0, b2, 0, qkvp, TD_, 0, nullptr,
        mha_in_b, mha_in_b, D_, nullptr, qh, kh);

    // 2) attention scores -> fp16; zsum; colsum; ctx mean (8-way split + atomics)
    tc_gemm<3><<<dim3(S_/128, S_/128, B_*NH_), 256, GSMEM>>>(
        qh, (long)S_*HD_, kh, (long)S_*HD_, nullptr, S_, (long)S_*S_, sc16,
        nullptr, nullptr, HD_, mask, nullptr, nullptr);
    zsum_kernel<<<B_*NH_*S_, 256>>>();
    colsum_kernel<<<dim3(B_*NH_, 2), 256>>>();
    cudaMemsetAsync(cmp, 0, sizeof(float) * (size_t)B_ * D_);
    ctxmean_kernel<<<dim3(B_*NH_, 8), 192>>>();

    // 3) embedding path
    idx_kernel<<<B_, 256>>>(mask);
    embed_kernel<<<B_, 256>>>(mha_out_w, mha_out_b, asp_w, asp_b, opi_w, opi_b,
                              ia_w, ia_b, io_w, io_b, out);

    // 4+5) build se1/se2 (both stacks, contiguous) + x passthrough
    build_se_kernel<<<BS_, 256>>>(x, out);

    // 6) decoder stacks, batched fwd+rev (z=2)
    for (int l = 0; l < NL_; l++) {
        cvt(fwd_iw + (size_t)l*DFF_*D_, b2, (size_t)DFF_*D_);
        cvt(rev_iw + (size_t)l*DFF_*D_, b2 + (size_t)DFF_*D_, (size_t)DFF_*D_);
        tc_gemm<1><<<dim3(DFF_/128, BS_/128, 2), 256, GSMEM>>>(
            a2, (long)BS_*D_, b2, (long)DFF_*D_, nullptr, DFF_, (long)BS_*DFF_, i2,
            fwd_ib + (size_t)l*DFF_, rev_ib + (size_t)l*DFF_, D_, nullptr, nullptr, nullptr);
        cvt(fwd_ow + (size_t)l*D_*DFF_, b2, (size_t)D_*DFF_);
        cvt(rev_ow + (size_t)l*D_*DFF_, b2 + (size_t)D_*DFF_, (size_t)D_*DFF_);
        tc_gemm<2><<<dim3(D_/128, BS_/128, 2), 256, GSMEM>>>(
            i2, (long)BS_*DFF_, b2, (long)D_*DFF_, t2, D_, (long)BS_*D_, nullptr,
            nullptr, nullptr, DFF_, nullptr, nullptr, nullptr);
        bool last = (l == NL_-1);
        float* lnout = last ? (out + O_SE1) : nullptr;
        float* hhp; cudaGetSymbolAddress((void**)&hhp, g_hh);
        ln_kernel<<<2*BS_, 256>>>(t2,
            fwd_ob + (size_t)l*D_, rev_ob + (size_t)l*D_,
            fwd_g  + (size_t)l*D_, rev_g  + (size_t)l*D_,
            fwd_bt + (size_t)l*D_, rev_bt + (size_t)l*D_,
            last ? lnout : hhp, last ? nullptr : a2);
    }

    // 7) batched classifier logits (O_LA and O_LO contiguous)
    logits_kernel<<<2*BS_, 256>>>(out + O_SE1, cls_a_w, cls_a_b, cls_o_w, cls_o_b, out + O_LA);
}